// round 8
// baseline (speedup 1.0000x reference)
#include <cuda_runtime.h>
#include <math.h>

#define Bn 4
#define Cc 64
#define Oo 64
#define Hh 128
#define Ww 128
#define HW (Hh*Ww)

// ---------------- device scratch ----------------
__device__ float g_xt[Bn*HW*Cc];      // x as [b][h][w][c]
__device__ float g_wt[9*Cc*Oo];       // dcn_w as [tap][c][o]
__device__ float g_ow[9*Cc*32];       // offset_w as [tap][c][jq][8], j = jq*7+idx (idx<7, j<27)
__device__ float g_offx[Bn*9*HW];
__device__ float g_offy[Bn*9*HW];
__device__ float g_mask[Bn*9*HW];
__device__ float g_stats[2*Oo];

// ---------------- f32x2 helpers ----------------
__device__ __forceinline__ unsigned long long f2pack(float lo, float hi) {
    unsigned long long r;
    asm("mov.b64 %0, {%1, %2};" : "=l"(r)
        : "r"(__float_as_uint(lo)), "r"(__float_as_uint(hi)));
    return r;
}
__device__ __forceinline__ void f2unpack(unsigned long long v, float &lo, float &hi) {
    unsigned int a, b;
    asm("mov.b64 {%0, %1}, %2;" : "=r"(a), "=r"(b) : "l"(v));
    lo = __uint_as_float(a); hi = __uint_as_float(b);
}
__device__ __forceinline__ void ffma2(unsigned long long &d,
                                      unsigned long long a, unsigned long long b) {
    asm("fma.rn.f32x2 %0, %1, %2, %0;" : "+l"(d) : "l"(a), "l"(b));
}

// ---------------- K0: NCHW -> NHWC ----------------
__global__ void k_transpose(const float* __restrict__ x) {
    __shared__ float tile[32][65];
    int b = blockIdx.y, hw0 = blockIdx.x * 32;
    int tx = threadIdx.x, ty = threadIdx.y;
#pragma unroll
    for (int cc = 0; cc < 8; cc++) {
        int c = cc * 8 + ty;
        tile[tx][c] = x[(b*Cc + c)*HW + hw0 + tx];
    }
    __syncthreads();
#pragma unroll
    for (int rr = 0; rr < 4; rr++) {
        int hw = rr * 8 + ty;
        float* dst = g_xt + (size_t)(b*HW + hw0 + hw) * Cc;
        dst[tx]      = tile[hw][tx];
        dst[tx + 32] = tile[hw][tx + 32];
    }
}

// ---------------- K0b: weight re-layouts ----------------
__global__ void k_wt(const float* __restrict__ dcn_w) {
    int i = blockIdx.x * 256 + threadIdx.x;
    if (i < 9*Cc*Oo) {
        int o = i & 63, c = (i >> 6) & 63, k = i >> 12;
        g_wt[i] = dcn_w[(o*Cc + c)*9 + k];
    }
}
__global__ void k_owt(const float* __restrict__ ow) {
    int i = blockIdx.x * 256 + threadIdx.x;
    if (i < 9*Cc*32) {
        int slot = i & 31, c = (i >> 5) & 63, tap = i >> 11;
        int ky = tap / 3, kx = tap % 3;
        int jq = slot >> 3, idx = slot & 7;
        int j = jq*7 + idx;
        g_ow[i] = (idx < 7 && j < 27) ? ow[((j*Cc + c)*3 + ky)*3 + kx] : 0.f;
    }
}

// ---------------- K1: offset conv — smem-staged x, L1-broadcast weights ----------------
// block = (b, h, px-half): 64 px; 128 threads.
__global__ void __launch_bounds__(128) k_offset(const float* __restrict__ ob) {
    __shared__ float xs[64*65];      // [c][px] stride 65  16.6 KB
    int t = threadIdx.x;
    int b = blockIdx.y, h = blockIdx.x, ph = blockIdx.z;
    int w0 = ph * 64;
    int lane = t & 31, wrp = t >> 5;
    int jq = wrp, ps = lane;
    int j0 = jq * 7;

    unsigned long long acc[8];       // [px 2][j-pair 4]
#pragma unroll
    for (int p = 0; p < 4; p++) {
        int j = j0 + 2*p;
        float lo = (j < 27)     ? __ldg(&ob[j])     : 0.f;
        float hi = (j + 1 < 27) ? __ldg(&ob[j + 1]) : 0.f;
        unsigned long long v = f2pack(lo, hi);
        acc[p] = v; acc[4 + p] = v;
    }

    for (int tap = 0; tap < 9; tap++) {
        int ky = tap / 3, kx = tap % 3;
        __syncthreads();
        // stage shifted x row: warp per pixel, lane = channel (coalesced 128B)
        int y = h + ky - 1;
        if ((unsigned)y < Hh) {
            const float* xrow = g_xt + (size_t)(b*Hh + y) * Ww * Cc;
#pragma unroll
            for (int pp = wrp; pp < 64; pp += 4) {
                int xq = w0 + pp + kx - 1;
                bool v = ((unsigned)xq < Ww);
                const float* src = xrow + (size_t)(v ? xq : 0) * Cc;
                float v0 = v ? src[lane]      : 0.f;
                float v1 = v ? src[lane + 32] : 0.f;
                xs[lane*65 + pp]        = v0;
                xs[(lane + 32)*65 + pp] = v1;
            }
        } else {
#pragma unroll
            for (int pp = wrp; pp < 64; pp += 4) {
                xs[lane*65 + pp]        = 0.f;
                xs[(lane + 32)*65 + pp] = 0.f;
            }
        }
        __syncthreads();
        // GEMM: per c: 2 scalar LDS + 2 broadcast LDG.128 (L1) + 8 FFMA2
        // g_ow row stride per c = 32 floats = 8 ulonglong2
        const ulonglong2* wtap = (const ulonglong2*)(g_ow + tap*64*32 + jq*8);
#pragma unroll 4
        for (int c = 0; c < 64; c++) {
            const float* srow = xs + c*65;
            float s0 = srow[ps], s1 = srow[ps + 32];
            unsigned long long p0 = f2pack(s0, s0), p1 = f2pack(s1, s1);
            ulonglong2 wA = wtap[c*8], wB = wtap[c*8 + 1];
            ffma2(acc[0], p0, wA.x); ffma2(acc[1], p0, wA.y);
            ffma2(acc[2], p0, wB.x); ffma2(acc[3], p0, wB.y);
            ffma2(acc[4], p1, wA.x); ffma2(acc[5], p1, wA.y);
            ffma2(acc[6], p1, wB.x); ffma2(acc[7], p1, wB.y);
        }
    }
#pragma unroll
    for (int k = 0; k < 2; k++) {
        int w = w0 + ps + 32*k;
        int base = (b*9)*HW + h*Ww + w;
        float a[8];
#pragma unroll
        for (int p = 0; p < 4; p++) f2unpack(acc[k*4 + p], a[2*p], a[2*p+1]);
#pragma unroll
        for (int u = 0; u < 7; u++) {
            int j = j0 + u;
            if (j < 9)        g_offx[base + j*HW]        = a[u];
            else if (j < 18)  g_offy[base + (j - 9)*HW]  = a[u];
            else if (j < 27)  g_mask[base + (j - 18)*HW] = 1.f / (1.f + expf(-a[u]));
        }
    }
}

// ---------------- K2: DCN sampling + GEMM — L1-broadcast weights ----------------
// block = (b, h, px-quarter): 32 px x 64 o; 128 threads.
__global__ void __launch_bounds__(128, 8) k_dcn(const float* __restrict__ dcn_b,
                                                float* __restrict__ out) {
    __shared__ float samp[64*33];    // [c][p] stride 33  8.6 KB only

    int t    = threadIdx.x;
    int bb   = blockIdx.y, h = blockIdx.x, pq = blockIdx.z;
    int lane = t & 31,  wrp = t >> 5;
    int og   = t >> 4,  ps  = t & 15;

    unsigned long long acc[8];
#pragma unroll
    for (int i = 0; i < 8; i++) acc[i] = 0ULL;

    for (int tap = 0; tap < 9; tap++) {
        int ky = tap / 3, kx = tap % 3;
        __syncthreads();                       // protect samp from prev GEMM
#pragma unroll
        for (int i = 0; i < 8; i += 2) {
            int pp0 = wrp*8 + i, pp1 = pp0 + 1;
            int wq0 = pq*32 + pp0, wq1 = wq0 + 1;
            int ob0 = ((bb*9 + tap)*Hh + h)*Ww + wq0;
            int ob1 = ob0 + 1;
            float oy0 = __ldg(&g_offy[ob0]), ox0 = __ldg(&g_offx[ob0]), m0 = __ldg(&g_mask[ob0]);
            float oy1 = __ldg(&g_offy[ob1]), ox1 = __ldg(&g_offx[ob1]), m1 = __ldg(&g_mask[ob1]);

            float py0 = (float)(h - 1 + ky) + oy0, px0 = (float)(wq0 - 1 + kx) + ox0;
            float py1 = (float)(h - 1 + ky) + oy1, px1 = (float)(wq1 - 1 + kx) + ox1;
            float y0f0 = floorf(py0), x0f0 = floorf(px0);
            float y0f1 = floorf(py1), x0f1 = floorf(px1);
            float wy0 = py0 - y0f0, wx0 = px0 - x0f0;
            float wy1 = py1 - y0f1, wx1 = px1 - x0f1;
            float hy00 = (y0f0 >=  0.f && y0f0 <= 127.f) ? (1.f - wy0)*m0 : 0.f;
            float hy10 = (y0f0 >= -1.f && y0f0 <= 126.f) ? wy0*m0        : 0.f;
            float gx00 = (x0f0 >=  0.f && x0f0 <= 127.f) ? (1.f - wx0)   : 0.f;
            float gx10 = (x0f0 >= -1.f && x0f0 <= 126.f) ? wx0           : 0.f;
            float hy01 = (y0f1 >=  0.f && y0f1 <= 127.f) ? (1.f - wy1)*m1 : 0.f;
            float hy11 = (y0f1 >= -1.f && y0f1 <= 126.f) ? wy1*m1        : 0.f;
            float gx01 = (x0f1 >=  0.f && x0f1 <= 127.f) ? (1.f - wx1)   : 0.f;
            float gx11 = (x0f1 >= -1.f && x0f1 <= 126.f) ? wx1           : 0.f;
            int iy00 = (int)fminf(fmaxf(y0f0,      0.f), 127.f);
            int iy10 = (int)fminf(fmaxf(y0f0 + 1.f,0.f), 127.f);
            int ix00 = (int)fminf(fmaxf(x0f0,      0.f), 127.f);
            int ix10 = (int)fminf(fmaxf(x0f0 + 1.f,0.f), 127.f);
            int iy01 = (int)fminf(fmaxf(y0f1,      0.f), 127.f);
            int iy11 = (int)fminf(fmaxf(y0f1 + 1.f,0.f), 127.f);
            int ix01 = (int)fminf(fmaxf(x0f1,      0.f), 127.f);
            int ix11 = (int)fminf(fmaxf(x0f1 + 1.f,0.f), 127.f);
            float wA0 = hy00*gx00, wB0 = hy00*gx10, wC0 = hy10*gx00, wD0 = hy10*gx10;
            float wA1 = hy01*gx01, wB1 = hy01*gx11, wC1 = hy11*gx01, wD1 = hy11*gx11;
            const float* A0 = g_xt + (size_t)((bb*Hh + iy00)*Ww + ix00) * Cc;
            const float* B0 = g_xt + (size_t)((bb*Hh + iy00)*Ww + ix10) * Cc;
            const float* C0 = g_xt + (size_t)((bb*Hh + iy10)*Ww + ix00) * Cc;
            const float* D0 = g_xt + (size_t)((bb*Hh + iy10)*Ww + ix10) * Cc;
            const float* A1 = g_xt + (size_t)((bb*Hh + iy01)*Ww + ix01) * Cc;
            const float* B1 = g_xt + (size_t)((bb*Hh + iy01)*Ww + ix11) * Cc;
            const float* C1 = g_xt + (size_t)((bb*Hh + iy11)*Ww + ix01) * Cc;
            const float* D1 = g_xt + (size_t)((bb*Hh + iy11)*Ww + ix11) * Cc;
            float a0 = A0[lane],    b0 = B0[lane],    c0 = C0[lane],    d0 = D0[lane];
            float e0 = A0[lane+32], f0 = B0[lane+32], g0 = C0[lane+32], q0 = D0[lane+32];
            float a1 = A1[lane],    b1 = B1[lane],    c1 = C1[lane],    d1 = D1[lane];
            float e1 = A1[lane+32], f1 = B1[lane+32], g1 = C1[lane+32], q1 = D1[lane+32];
            samp[lane*33 + pp0]      = wA0*a0 + wB0*b0 + wC0*c0 + wD0*d0;
            samp[(lane+32)*33 + pp0] = wA0*e0 + wB0*f0 + wC0*g0 + wD0*q0;
            samp[lane*33 + pp1]      = wA1*a1 + wB1*b1 + wC1*c1 + wD1*d1;
            samp[(lane+32)*33 + pp1] = wA1*e1 + wB1*f1 + wC1*g1 + wD1*q1;
        }
        __syncthreads();
        // GEMM: per c: 2 scalar LDS + 2 broadcast LDG.128 (L1) + 8 FFMA2
        // g_wt row stride per c = 64 floats = 16 ulonglong2
        const ulonglong2* wtap = (const ulonglong2*)(g_wt + tap*4096 + og*8);
#pragma unroll 4
        for (int c = 0; c < 64; c++) {
            const float* srow = samp + c*33;
            float s0 = srow[ps], s1 = srow[ps + 16];
            unsigned long long p0 = f2pack(s0, s0), p1 = f2pack(s1, s1);
            ulonglong2 wa = wtap[c*16], wb = wtap[c*16 + 1];
            ffma2(acc[0], p0, wa.x); ffma2(acc[1], p0, wa.y);
            ffma2(acc[2], p0, wb.x); ffma2(acc[3], p0, wb.y);
            ffma2(acc[4], p1, wa.x); ffma2(acc[5], p1, wa.y);
            ffma2(acc[6], p1, wb.x); ffma2(acc[7], p1, wb.y);
        }
    }
#pragma unroll
    for (int k = 0; k < 2; k++) {
        int p = pq*32 + ps + 16*k;
#pragma unroll
        for (int j = 0; j < 4; j++) {
            float lo, hi; f2unpack(acc[k*4 + j], lo, hi);
            int o = og*8 + 2*j;
            out[(size_t)(bb*Oo + o    )*HW + h*Ww + p] = lo + __ldg(&dcn_b[o]);
            out[(size_t)(bb*Oo + o + 1)*HW + h*Ww + p] = hi + __ldg(&dcn_b[o+1]);
        }
    }
}

// ---------------- K3: per-channel stats ----------------
__global__ void k_stats(const float* __restrict__ out) {
    __shared__ float ssum[512], ssq[512];
    int o = blockIdx.x, t = threadIdx.x;
    float s = 0.f, q = 0.f;
    for (int i = t; i < Bn*HW; i += 512) {
        int b = i >> 14, j = i & (HW - 1);
        float v = out[(size_t)(b*Oo + o)*HW + j];
        s += v; q += v*v;
    }
    ssum[t] = s; ssq[t] = q;
    __syncthreads();
    for (int st = 256; st > 0; st >>= 1) {
        if (t < st) { ssum[t] += ssum[t+st]; ssq[t] += ssq[t+st]; }
        __syncthreads();
    }
    if (t == 0) { g_stats[o] = ssum[0]; g_stats[64 + o] = ssq[0]; }
}

// ---------------- K4: BN + ReLU ----------------
__global__ void k_norm(float* __restrict__ out,
                       const float* __restrict__ gamma,
                       const float* __restrict__ beta) {
    int i4 = blockIdx.x * 256 + threadIdx.x;
    int idx = i4 * 4;
    int o = (idx >> 14) & 63;
    const float invN = 1.f / (float)(Bn*HW);
    float s = g_stats[o], q = g_stats[64 + o];
    float mu  = s * invN;
    float var = fmaf(q, invN, -mu*mu);
    float rstd = rsqrtf(var + 1e-5f) * __ldg(&gamma[o]);
    float bt = __ldg(&beta[o]);
    float4 v = *(float4*)(out + idx);
    v.x = fmaxf((v.x - mu)*rstd + bt, 0.f);
    v.y = fmaxf((v.y - mu)*rstd + bt, 0.f);
    v.z = fmaxf((v.z - mu)*rstd + bt, 0.f);
    v.w = fmaxf((v.w - mu)*rstd + bt, 0.f);
    *(float4*)(out + idx) = v;
}

// ---------------- launcher ----------------
extern "C" void kernel_launch(void* const* d_in, const int* in_sizes, int n_in,
                              void* d_out, int out_size) {
    const float* x        = (const float*)d_in[0];
    const float* offset_w = (const float*)d_in[1];
    const float* offset_b = (const float*)d_in[2];
    const float* dcn_w    = (const float*)d_in[3];
    const float* dcn_b    = (const float*)d_in[4];
    const float* gamma    = (const float*)d_in[5];
    const float* beta     = (const float*)d_in[6];
    float* out = (float*)d_out;

    k_transpose<<<dim3(512, Bn), dim3(32, 8)>>>(x);
    k_wt<<<144, 256>>>(dcn_w);
    k_owt<<<72, 256>>>(offset_w);
    k_offset<<<dim3(Hh, Bn, 2), 128>>>(offset_b);
    k_dcn<<<dim3(Hh, Bn, 4), 128>>>(dcn_b, out);
    k_stats<<<Oo, 512>>>(out);
    k_norm<<<(Bn*Oo*HW)/1024, 256>>>(out, gamma, beta);
}

// round 10
// speedup vs baseline: 1.3099x; 1.3099x over previous
#include <cuda_runtime.h>
#include <math.h>

#define Bn 4
#define Cc 64
#define Oo 64
#define Hh 128
#define Ww 128
#define HW (Hh*Ww)

typedef unsigned long long ull;

// ---------------- device scratch ----------------
__device__ float g_xt[Bn*HW*Cc];      // x as [b][h][w][c]
__device__ float g_wt[9*Cc*Oo];       // dcn_w as [tap][c][o]
__device__ float g_ow[9*Cc*32];       // offset_w as [tap][c][jq][8]
__device__ float g_offx[Bn*9*HW];
__device__ float g_offy[Bn*9*HW];
__device__ float g_mask[Bn*9*HW];
__device__ float g_stats[2*Oo];

// ---------------- f32x2 helpers ----------------
__device__ __forceinline__ ull f2pack(float lo, float hi) {
    ull r;
    asm("mov.b64 %0, {%1, %2};" : "=l"(r)
        : "r"(__float_as_uint(lo)), "r"(__float_as_uint(hi)));
    return r;
}
__device__ __forceinline__ void f2unpack(ull v, float &lo, float &hi) {
    unsigned int a, b;
    asm("mov.b64 {%0, %1}, %2;" : "=r"(a), "=r"(b) : "l"(v));
    lo = __uint_as_float(a); hi = __uint_as_float(b);
}
__device__ __forceinline__ void ffma2(ull &d, ull a, ull b) {
    asm("fma.rn.f32x2 %0, %1, %2, %0;" : "+l"(d) : "l"(a), "l"(b));
}

// ---------------- K0: NCHW -> NHWC ----------------
__global__ void k_transpose(const float* __restrict__ x) {
    __shared__ float tile[32][65];
    int b = blockIdx.y, hw0 = blockIdx.x * 32;
    int tx = threadIdx.x, ty = threadIdx.y;
#pragma unroll
    for (int cc = 0; cc < 8; cc++) {
        int c = cc * 8 + ty;
        tile[tx][c] = x[(b*Cc + c)*HW + hw0 + tx];
    }
    __syncthreads();
#pragma unroll
    for (int rr = 0; rr < 4; rr++) {
        int hw = rr * 8 + ty;
        float* dst = g_xt + (size_t)(b*HW + hw0 + hw) * Cc;
        dst[tx]      = tile[hw][tx];
        dst[tx + 32] = tile[hw][tx + 32];
    }
}

// ---------------- K0b: weight re-layouts ----------------
__global__ void k_wt(const float* __restrict__ dcn_w) {
    int i = blockIdx.x * 256 + threadIdx.x;
    if (i < 9*Cc*Oo) {
        int o = i & 63, c = (i >> 6) & 63, k = i >> 12;
        g_wt[i] = dcn_w[(o*Cc + c)*9 + k];
    }
}
__global__ void k_owt(const float* __restrict__ ow) {
    int i = blockIdx.x * 256 + threadIdx.x;
    if (i < 9*Cc*32) {
        int slot = i & 31, c = (i >> 5) & 63, tap = i >> 11;
        int ky = tap / 3, kx = tap % 3;
        int jq = slot >> 3, idx = slot & 7;
        int j = jq*7 + idx;
        g_ow[i] = (idx < 7 && j < 27) ? ow[((j*Cc + c)*3 + ky)*3 + kx] : 0.f;
    }
}

// ---------------- K1: offset conv — R6 structure (smem wsm + xs) ----------------
__global__ void __launch_bounds__(128) k_offset(const float* __restrict__ ob) {
    __shared__ float wsm[64*32];     // [c][jq][8]   8 KB; per-c stride = 32 floats = 8 ull2
    __shared__ float xs[64*65];      // [c][px] stride 65  16.6 KB
    int t = threadIdx.x;
    int b = blockIdx.y, h = blockIdx.x, ph = blockIdx.z;
    int w0 = ph * 64;
    int lane = t & 31, wrp = t >> 5;
    int jq = wrp, ps = lane;
    int j0 = jq * 7;

    ull acc[8];
#pragma unroll
    for (int p = 0; p < 4; p++) {
        int j = j0 + 2*p;
        float lo = (j < 27)     ? __ldg(&ob[j])     : 0.f;
        float hi = (j + 1 < 27) ? __ldg(&ob[j + 1]) : 0.f;
        ull v = f2pack(lo, hi);
        acc[p] = v; acc[4 + p] = v;
    }

    for (int tap = 0; tap < 9; tap++) {
        int ky = tap / 3, kx = tap % 3;
        __syncthreads();
        {
            const float4* src = (const float4*)(g_ow + tap*64*32);
            float4* dst = (float4*)wsm;
            dst[t]       = src[t];
            dst[t + 128] = src[t + 128];
            dst[t + 256] = src[t + 256];
            dst[t + 384] = src[t + 384];
        }
        int y = h + ky - 1;
        if ((unsigned)y < Hh) {
            const float* xrow = g_xt + (size_t)(b*Hh + y) * Ww * Cc;
#pragma unroll
            for (int pp = wrp; pp < 64; pp += 4) {
                int xq = w0 + pp + kx - 1;
                bool v = ((unsigned)xq < Ww);
                const float* src = xrow + (size_t)(v ? xq : 0) * Cc;
                float v0 = v ? src[lane]      : 0.f;
                float v1 = v ? src[lane + 32] : 0.f;
                xs[lane*65 + pp]        = v0;
                xs[(lane + 32)*65 + pp] = v1;
            }
        } else {
#pragma unroll
            for (int pp = wrp; pp < 64; pp += 4) {
                xs[lane*65 + pp]        = 0.f;
                xs[(lane + 32)*65 + pp] = 0.f;
            }
        }
        __syncthreads();
        // per-c stride = 32 floats = 8 ulonglong2  -> wtap[c*8]
        const ulonglong2* wtap = (const ulonglong2*)(wsm + jq*8);
#pragma unroll 4
        for (int c = 0; c < 64; c++) {
            const float* srow = xs + c*65;
            float s0 = srow[ps], s1 = srow[ps + 32];
            ull p0 = f2pack(s0, s0), p1 = f2pack(s1, s1);
            ulonglong2 wA = wtap[c*8], wB = wtap[c*8 + 1];
            ffma2(acc[0], p0, wA.x); ffma2(acc[1], p0, wA.y);
            ffma2(acc[2], p0, wB.x); ffma2(acc[3], p0, wB.y);
            ffma2(acc[4], p1, wA.x); ffma2(acc[5], p1, wA.y);
            ffma2(acc[6], p1, wB.x); ffma2(acc[7], p1, wB.y);
        }
    }
#pragma unroll
    for (int k = 0; k < 2; k++) {
        int w = w0 + ps + 32*k;
        int base = (b*9)*HW + h*Ww + w;
        float a[8];
#pragma unroll
        for (int p = 0; p < 4; p++) f2unpack(acc[k*4 + p], a[2*p], a[2*p+1]);
#pragma unroll
        for (int u = 0; u < 7; u++) {
            int j = j0 + u;
            if (j < 9)        g_offx[base + j*HW]        = a[u];
            else if (j < 18)  g_offy[base + (j - 9)*HW]  = a[u];
            else if (j < 27)  g_mask[base + (j - 18)*HW] = 1.f / (1.f + expf(-a[u]));
        }
    }
}

// ---------------- K2: DCN — 256 thr, 64 o x 64 px, duplicated-pair samp ----------------
// dynamic smem: ws float[64*64] (16 KB) + samp2 ull[64*65] (33.3 KB) = 49.7 KB
#define DCN_SMEM (64*64*4 + 64*65*8)
__global__ void __launch_bounds__(256, 4) k_dcn(const float* __restrict__ dcn_b,
                                                float* __restrict__ out) {
    extern __shared__ float smem[];
    float* ws   = smem;                       // [c][o]; per-c stride = 64 floats = 16 ull2
    ull*   samp2 = (ull*)(smem + 64*64);      // [c][px] pairs, stride 65

    int t    = threadIdx.x;
    int bb   = blockIdx.y, h = blockIdx.x, pq = blockIdx.z;
    int lane = t & 31,  wrp = t >> 5;
    int og   = wrp,  ps = lane;               // warp-uniform og -> broadcast weights

    ull acc[8];
#pragma unroll
    for (int i = 0; i < 8; i++) acc[i] = 0ULL;

    for (int tap = 0; tap < 9; tap++) {
        int ky = tap / 3, kx = tap % 3;
        __syncthreads();
        {   // stage tap weights: 1024 float4, 4 per thread
            const float4* src = (const float4*)(g_wt + tap*4096);
            float4* dst = (float4*)ws;
#pragma unroll
            for (int i = 0; i < 4; i++) dst[t + 256*i] = src[t + 256*i];
        }
        // gather: warp owns 8 px, 2-px batches
#pragma unroll
        for (int i = 0; i < 8; i += 2) {
            int pp0 = wrp*8 + i, pp1 = pp0 + 1;
            int wq0 = pq*64 + pp0, wq1 = wq0 + 1;
            int ob0 = ((bb*9 + tap)*Hh + h)*Ww + wq0;
            int ob1 = ob0 + 1;
            float oy0 = __ldg(&g_offy[ob0]), ox0 = __ldg(&g_offx[ob0]), m0 = __ldg(&g_mask[ob0]);
            float oy1 = __ldg(&g_offy[ob1]), ox1 = __ldg(&g_offx[ob1]), m1 = __ldg(&g_mask[ob1]);

            float py0 = (float)(h - 1 + ky) + oy0, px0 = (float)(wq0 - 1 + kx) + ox0;
            float py1 = (float)(h - 1 + ky) + oy1, px1 = (float)(wq1 - 1 + kx) + ox1;
            float y0f0 = floorf(py0), x0f0 = floorf(px0);
            float y0f1 = floorf(py1), x0f1 = floorf(px1);
            float wy0 = py0 - y0f0, wx0 = px0 - x0f0;
            float wy1 = py1 - y0f1, wx1 = px1 - x0f1;
            float hy00 = (y0f0 >=  0.f && y0f0 <= 127.f) ? (1.f - wy0)*m0 : 0.f;
            float hy10 = (y0f0 >= -1.f && y0f0 <= 126.f) ? wy0*m0        : 0.f;
            float gx00 = (x0f0 >=  0.f && x0f0 <= 127.f) ? (1.f - wx0)   : 0.f;
            float gx10 = (x0f0 >= -1.f && x0f0 <= 126.f) ? wx0           : 0.f;
            float hy01 = (y0f1 >=  0.f && y0f1 <= 127.f) ? (1.f - wy1)*m1 : 0.f;
            float hy11 = (y0f1 >= -1.f && y0f1 <= 126.f) ? wy1*m1        : 0.f;
            float gx01 = (x0f1 >=  0.f && x0f1 <= 127.f) ? (1.f - wx1)   : 0.f;
            float gx11 = (x0f1 >= -1.f && x0f1 <= 126.f) ? wx1           : 0.f;
            int iy00 = (int)fminf(fmaxf(y0f0,      0.f), 127.f);
            int iy10 = (int)fminf(fmaxf(y0f0 + 1.f,0.f), 127.f);
            int ix00 = (int)fminf(fmaxf(x0f0,      0.f), 127.f);
            int ix10 = (int)fminf(fmaxf(x0f0 + 1.f,0.f), 127.f);
            int iy01 = (int)fminf(fmaxf(y0f1,      0.f), 127.f);
            int iy11 = (int)fminf(fmaxf(y0f1 + 1.f,0.f), 127.f);
            int ix01 = (int)fminf(fmaxf(x0f1,      0.f), 127.f);
            int ix11 = (int)fminf(fmaxf(x0f1 + 1.f,0.f), 127.f);
            float wA0 = hy00*gx00, wB0 = hy00*gx10, wC0 = hy10*gx00, wD0 = hy10*gx10;
            float wA1 = hy01*gx01, wB1 = hy01*gx11, wC1 = hy11*gx01, wD1 = hy11*gx11;
            const float* A0 = g_xt + (size_t)((bb*Hh + iy00)*Ww + ix00) * Cc;
            const float* B0 = g_xt + (size_t)((bb*Hh + iy00)*Ww + ix10) * Cc;
            const float* C0 = g_xt + (size_t)((bb*Hh + iy10)*Ww + ix00) * Cc;
            const float* D0 = g_xt + (size_t)((bb*Hh + iy10)*Ww + ix10) * Cc;
            const float* A1 = g_xt + (size_t)((bb*Hh + iy01)*Ww + ix01) * Cc;
            const float* B1 = g_xt + (size_t)((bb*Hh + iy01)*Ww + ix11) * Cc;
            const float* C1 = g_xt + (size_t)((bb*Hh + iy11)*Ww + ix01) * Cc;
            const float* D1 = g_xt + (size_t)((bb*Hh + iy11)*Ww + ix11) * Cc;
            float a0 = A0[lane],    b0 = B0[lane],    c0 = C0[lane],    d0 = D0[lane];
            float e0 = A0[lane+32], f0 = B0[lane+32], g0 = C0[lane+32], q0 = D0[lane+32];
            float a1 = A1[lane],    b1 = B1[lane],    c1 = C1[lane],    d1 = D1[lane];
            float e1 = A1[lane+32], f1 = B1[lane+32], g1 = C1[lane+32], q1 = D1[lane+32];
            float s00 = wA0*a0 + wB0*b0 + wC0*c0 + wD0*d0;
            float s01 = wA0*e0 + wB0*f0 + wC0*g0 + wD0*q0;
            float s10 = wA1*a1 + wB1*b1 + wC1*c1 + wD1*d1;
            float s11 = wA1*e1 + wB1*f1 + wC1*g1 + wD1*q1;
            samp2[lane*65 + pp0]        = f2pack(s00, s00);
            samp2[(lane + 32)*65 + pp0] = f2pack(s01, s01);
            samp2[lane*65 + pp1]        = f2pack(s10, s10);
            samp2[(lane + 32)*65 + pp1] = f2pack(s11, s11);
        }
        __syncthreads();
        // GEMM: per c: 2 LDS.64 + 2 broadcast LDS.128 + 8 FFMA2
        // ws per-c stride = 64 floats = 16 ulonglong2 -> wtap[c*16]
        const ulonglong2* wtap = (const ulonglong2*)(ws + og*8);
#pragma unroll 4
        for (int c = 0; c < 64; c++) {
            const ull* srow = samp2 + c*65;
            ull p0 = srow[ps], p1 = srow[ps + 32];
            ulonglong2 wa = wtap[c*16], wb = wtap[c*16 + 1];
            ffma2(acc[0], p0, wa.x); ffma2(acc[1], p0, wa.y);
            ffma2(acc[2], p0, wb.x); ffma2(acc[3], p0, wb.y);
            ffma2(acc[4], p1, wa.x); ffma2(acc[5], p1, wa.y);
            ffma2(acc[6], p1, wb.x); ffma2(acc[7], p1, wb.y);
        }
    }
#pragma unroll
    for (int k = 0; k < 2; k++) {
        int p = pq*64 + ps + 32*k;
#pragma unroll
        for (int j = 0; j < 4; j++) {
            float lo, hi; f2unpack(acc[k*4 + j], lo, hi);
            int o = og*8 + 2*j;
            out[(size_t)(bb*Oo + o    )*HW + h*Ww + p] = lo + __ldg(&dcn_b[o]);
            out[(size_t)(bb*Oo + o + 1)*HW + h*Ww + p] = hi + __ldg(&dcn_b[o+1]);
        }
    }
}

// ---------------- K3: per-channel stats ----------------
__global__ void k_stats(const float* __restrict__ out) {
    __shared__ float ssum[512], ssq[512];
    int o = blockIdx.x, t = threadIdx.x;
    float s = 0.f, q = 0.f;
    for (int i = t; i < Bn*HW; i += 512) {
        int b = i >> 14, j = i & (HW - 1);
        float v = out[(size_t)(b*Oo + o)*HW + j];
        s += v; q += v*v;
    }
    ssum[t] = s; ssq[t] = q;
    __syncthreads();
    for (int st = 256; st > 0; st >>= 1) {
        if (t < st) { ssum[t] += ssum[t+st]; ssq[t] += ssq[t+st]; }
        __syncthreads();
    }
    if (t == 0) { g_stats[o] = ssum[0]; g_stats[64 + o] = ssq[0]; }
}

// ---------------- K4: BN + ReLU ----------------
__global__ void k_norm(float* __restrict__ out,
                       const float* __restrict__ gamma,
                       const float* __restrict__ beta) {
    int i4 = blockIdx.x * 256 + threadIdx.x;
    int idx = i4 * 4;
    int o = (idx >> 14) & 63;
    const float invN = 1.f / (float)(Bn*HW);
    float s = g_stats[o], q = g_stats[64 + o];
    float mu  = s * invN;
    float var = fmaf(q, invN, -mu*mu);
    float rstd = rsqrtf(var + 1e-5f) * __ldg(&gamma[o]);
    float bt = __ldg(&beta[o]);
    float4 v = *(float4*)(out + idx);
    v.x = fmaxf((v.x - mu)*rstd + bt, 0.f);
    v.y = fmaxf((v.y - mu)*rstd + bt, 0.f);
    v.z = fmaxf((v.z - mu)*rstd + bt, 0.f);
    v.w = fmaxf((v.w - mu)*rstd + bt, 0.f);
    *(float4*)(out + idx) = v;
}

// ---------------- launcher ----------------
extern "C" void kernel_launch(void* const* d_in, const int* in_sizes, int n_in,
                              void* d_out, int out_size) {
    const float* x        = (const float*)d_in[0];
    const float* offset_w = (const float*)d_in[1];
    const float* offset_b = (const float*)d_in[2];
    const float* dcn_w    = (const float*)d_in[3];
    const float* dcn_b    = (const float*)d_in[4];
    const float* gamma    = (const float*)d_in[5];
    const float* beta     = (const float*)d_in[6];
    float* out = (float*)d_out;

    cudaFuncSetAttribute(k_dcn, cudaFuncAttributeMaxDynamicSharedMemorySize, DCN_SMEM);

    k_transpose<<<dim3(512, Bn), dim3(32, 8)>>>(x);
    k_wt<<<144, 256>>>(dcn_w);
    k_owt<<<72, 256>>>(offset_w);
    k_offset<<<dim3(Hh, Bn, 2), 128>>>(offset_b);
    k_dcn<<<dim3(Hh, Bn, 2), 256, DCN_SMEM>>>(dcn_b, out);
    k_stats<<<Oo, 512>>>(out);
    k_norm<<<(Bn*Oo*HW)/1024, 256>>>(out, gamma, beta);
}

// round 11
// speedup vs baseline: 1.4754x; 1.1264x over previous
#include <cuda_runtime.h>
#include <math.h>

#define Bn 4
#define Cc 64
#define Oo 64
#define Hh 128
#define Ww 128
#define HW (Hh*Ww)

typedef unsigned long long ull;

// ---------------- device scratch ----------------
__device__ float g_xt[Bn*HW*Cc];      // x as [b][h][w][c]
__device__ float g_wt[9*Cc*Oo];       // dcn_w as [tap][c][o]
__device__ float g_ow[9*Cc*32];       // offset_w as [tap][c][jq][8]
__device__ float g_offx[Bn*9*HW];
__device__ float g_offy[Bn*9*HW];
__device__ float g_mask[Bn*9*HW];
__device__ float g_part[2*Oo*8];      // partial sums [sum|sq][o][part]
__device__ float g_stats[2*Oo];

// ---------------- f32x2 helpers ----------------
__device__ __forceinline__ ull f2pack(float lo, float hi) {
    ull r;
    asm("mov.b64 %0, {%1, %2};" : "=l"(r)
        : "r"(__float_as_uint(lo)), "r"(__float_as_uint(hi)));
    return r;
}
__device__ __forceinline__ void f2unpack(ull v, float &lo, float &hi) {
    unsigned int a, b;
    asm("mov.b64 {%0, %1}, %2;" : "=r"(a), "=r"(b) : "l"(v));
    lo = __uint_as_float(a); hi = __uint_as_float(b);
}
__device__ __forceinline__ void ffma2(ull &d, ull a, ull b) {
    asm("fma.rn.f32x2 %0, %1, %2, %0;" : "+l"(d) : "l"(a), "l"(b));
}

// ---------------- K0: NCHW -> NHWC ----------------
__global__ void k_transpose(const float* __restrict__ x) {
    __shared__ float tile[32][65];
    int b = blockIdx.y, hw0 = blockIdx.x * 32;
    int tx = threadIdx.x, ty = threadIdx.y;
#pragma unroll
    for (int cc = 0; cc < 8; cc++) {
        int c = cc * 8 + ty;
        tile[tx][c] = x[(b*Cc + c)*HW + hw0 + tx];
    }
    __syncthreads();
#pragma unroll
    for (int rr = 0; rr < 4; rr++) {
        int hw = rr * 8 + ty;
        float* dst = g_xt + (size_t)(b*HW + hw0 + hw) * Cc;
        dst[tx]      = tile[hw][tx];
        dst[tx + 32] = tile[hw][tx + 32];
    }
}

// ---------------- K0b: weight re-layouts ----------------
__global__ void k_wt(const float* __restrict__ dcn_w) {
    int i = blockIdx.x * 256 + threadIdx.x;
    if (i < 9*Cc*Oo) {
        int o = i & 63, c = (i >> 6) & 63, k = i >> 12;
        g_wt[i] = dcn_w[(o*Cc + c)*9 + k];
    }
}
__global__ void k_owt(const float* __restrict__ ow) {
    int i = blockIdx.x * 256 + threadIdx.x;
    if (i < 9*Cc*32) {
        int slot = i & 31, c = (i >> 5) & 63, tap = i >> 11;
        int ky = tap / 3, kx = tap % 3;
        int jq = slot >> 3, idx = slot & 7;
        int j = jq*7 + idx;
        g_ow[i] = (idx < 7 && j < 27) ? ow[((j*Cc + c)*3 + ky)*3 + kx] : 0.f;
    }
}

// ---------------- K1: offset conv — verified best (75.7us) ----------------
__global__ void __launch_bounds__(128) k_offset(const float* __restrict__ ob) {
    __shared__ float wsm[64*32];     // [c][jq][8]   8 KB; per-c stride = 32 floats = 8 ull2
    __shared__ float xs[64*65];      // [c][px] stride 65  16.6 KB
    int t = threadIdx.x;
    int b = blockIdx.y, h = blockIdx.x, ph = blockIdx.z;
    int w0 = ph * 64;
    int lane = t & 31, wrp = t >> 5;
    int jq = wrp, ps = lane;
    int j0 = jq * 7;

    ull acc[8];
#pragma unroll
    for (int p = 0; p < 4; p++) {
        int j = j0 + 2*p;
        float lo = (j < 27)     ? __ldg(&ob[j])     : 0.f;
        float hi = (j + 1 < 27) ? __ldg(&ob[j + 1]) : 0.f;
        ull v = f2pack(lo, hi);
        acc[p] = v; acc[4 + p] = v;
    }

    for (int tap = 0; tap < 9; tap++) {
        int ky = tap / 3, kx = tap % 3;
        __syncthreads();
        {
            const float4* src = (const float4*)(g_ow + tap*64*32);
            float4* dst = (float4*)wsm;
            dst[t]       = src[t];
            dst[t + 128] = src[t + 128];
            dst[t + 256] = src[t + 256];
            dst[t + 384] = src[t + 384];
        }
        int y = h + ky - 1;
        if ((unsigned)y < Hh) {
            const float* xrow = g_xt + (size_t)(b*Hh + y) * Ww * Cc;
#pragma unroll
            for (int pp = wrp; pp < 64; pp += 4) {
                int xq = w0 + pp + kx - 1;
                bool v = ((unsigned)xq < Ww);
                const float* src = xrow + (size_t)(v ? xq : 0) * Cc;
                float v0 = v ? src[lane]      : 0.f;
                float v1 = v ? src[lane + 32] : 0.f;
                xs[lane*65 + pp]        = v0;
                xs[(lane + 32)*65 + pp] = v1;
            }
        } else {
#pragma unroll
            for (int pp = wrp; pp < 64; pp += 4) {
                xs[lane*65 + pp]        = 0.f;
                xs[(lane + 32)*65 + pp] = 0.f;
            }
        }
        __syncthreads();
        // per-c stride = 32 floats = 8 ulonglong2  -> wtap[c*8]
        const ulonglong2* wtap = (const ulonglong2*)(wsm + jq*8);
#pragma unroll 4
        for (int c = 0; c < 64; c++) {
            const float* srow = xs + c*65;
            float s0 = srow[ps], s1 = srow[ps + 32];
            ull p0 = f2pack(s0, s0), p1 = f2pack(s1, s1);
            ulonglong2 wA = wtap[c*8], wB = wtap[c*8 + 1];
            ffma2(acc[0], p0, wA.x); ffma2(acc[1], p0, wA.y);
            ffma2(acc[2], p0, wB.x); ffma2(acc[3], p0, wB.y);
            ffma2(acc[4], p1, wA.x); ffma2(acc[5], p1, wA.y);
            ffma2(acc[6], p1, wB.x); ffma2(acc[7], p1, wB.y);
        }
    }
#pragma unroll
    for (int k = 0; k < 2; k++) {
        int w = w0 + ps + 32*k;
        int base = (b*9)*HW + h*Ww + w;
        float a[8];
#pragma unroll
        for (int p = 0; p < 4; p++) f2unpack(acc[k*4 + p], a[2*p], a[2*p+1]);
#pragma unroll
        for (int u = 0; u < 7; u++) {
            int j = j0 + u;
            if (j < 9)        g_offx[base + j*HW]        = a[u];
            else if (j < 18)  g_offy[base + (j - 9)*HW]  = a[u];
            else if (j < 27)  g_mask[base + (j - 18)*HW] = 1.f / (1.f + expf(-a[u]));
        }
    }
}

// ---------------- K2: DCN — verified-best 128thr/32px variant ----------------
__global__ void __launch_bounds__(128, 8) k_dcn(const float* __restrict__ dcn_b,
                                                float* __restrict__ out) {
    __shared__ float ws[64*64];      // [c][o]  16 KB
    __shared__ float samp[64*33];    // [c][p] stride 33

    int t    = threadIdx.x;
    int bb   = blockIdx.y, h = blockIdx.x, pq = blockIdx.z;
    int lane = t & 31,  wrp = t >> 5;
    int og   = t >> 4,  ps  = t & 15;

    ull acc[8];
#pragma unroll
    for (int i = 0; i < 8; i++) acc[i] = 0ULL;

    for (int tap = 0; tap < 9; tap++) {
        int ky = tap / 3, kx = tap % 3;
        __syncthreads();
        {
            const float4* src = (const float4*)(g_wt + tap*4096);
            float4* dst = (float4*)ws;
#pragma unroll
            for (int i = 0; i < 8; i++) dst[t + 128*i] = src[t + 128*i];
        }
#pragma unroll
        for (int i = 0; i < 8; i += 2) {
            int pp0 = wrp*8 + i, pp1 = pp0 + 1;
            int wq0 = pq*32 + pp0, wq1 = wq0 + 1;
            int ob0 = ((bb*9 + tap)*Hh + h)*Ww + wq0;
            int ob1 = ob0 + 1;
            float oy0 = __ldg(&g_offy[ob0]), ox0 = __ldg(&g_offx[ob0]), m0 = __ldg(&g_mask[ob0]);
            float oy1 = __ldg(&g_offy[ob1]), ox1 = __ldg(&g_offx[ob1]), m1 = __ldg(&g_mask[ob1]);

            float py0 = (float)(h - 1 + ky) + oy0, px0 = (float)(wq0 - 1 + kx) + ox0;
            float py1 = (float)(h - 1 + ky) + oy1, px1 = (float)(wq1 - 1 + kx) + ox1;
            float y0f0 = floorf(py0), x0f0 = floorf(px0);
            float y0f1 = floorf(py1), x0f1 = floorf(px1);
            float wy0 = py0 - y0f0, wx0 = px0 - x0f0;
            float wy1 = py1 - y0f1, wx1 = px1 - x0f1;
            float hy00 = (y0f0 >=  0.f && y0f0 <= 127.f) ? (1.f - wy0)*m0 : 0.f;
            float hy10 = (y0f0 >= -1.f && y0f0 <= 126.f) ? wy0*m0        : 0.f;
            float gx00 = (x0f0 >=  0.f && x0f0 <= 127.f) ? (1.f - wx0)   : 0.f;
            float gx10 = (x0f0 >= -1.f && x0f0 <= 126.f) ? wx0           : 0.f;
            float hy01 = (y0f1 >=  0.f && y0f1 <= 127.f) ? (1.f - wy1)*m1 : 0.f;
            float hy11 = (y0f1 >= -1.f && y0f1 <= 126.f) ? wy1*m1        : 0.f;
            float gx01 = (x0f1 >=  0.f && x0f1 <= 127.f) ? (1.f - wx1)   : 0.f;
            float gx11 = (x0f1 >= -1.f && x0f1 <= 126.f) ? wx1           : 0.f;
            int iy00 = (int)fminf(fmaxf(y0f0,      0.f), 127.f);
            int iy10 = (int)fminf(fmaxf(y0f0 + 1.f,0.f), 127.f);
            int ix00 = (int)fminf(fmaxf(x0f0,      0.f), 127.f);
            int ix10 = (int)fminf(fmaxf(x0f0 + 1.f,0.f), 127.f);
            int iy01 = (int)fminf(fmaxf(y0f1,      0.f), 127.f);
            int iy11 = (int)fminf(fmaxf(y0f1 + 1.f,0.f), 127.f);
            int ix01 = (int)fminf(fmaxf(x0f1,      0.f), 127.f);
            int ix11 = (int)fminf(fmaxf(x0f1 + 1.f,0.f), 127.f);
            float wA0 = hy00*gx00, wB0 = hy00*gx10, wC0 = hy10*gx00, wD0 = hy10*gx10;
            float wA1 = hy01*gx01, wB1 = hy01*gx11, wC1 = hy11*gx01, wD1 = hy11*gx11;
            const float* A0 = g_xt + (size_t)((bb*Hh + iy00)*Ww + ix00) * Cc;
            const float* B0 = g_xt + (size_t)((bb*Hh + iy00)*Ww + ix10) * Cc;
            const float* C0 = g_xt + (size_t)((bb*Hh + iy10)*Ww + ix00) * Cc;
            const float* D0 = g_xt + (size_t)((bb*Hh + iy10)*Ww + ix10) * Cc;
            const float* A1 = g_xt + (size_t)((bb*Hh + iy01)*Ww + ix01) * Cc;
            const float* B1 = g_xt + (size_t)((bb*Hh + iy01)*Ww + ix11) * Cc;
            const float* C1 = g_xt + (size_t)((bb*Hh + iy11)*Ww + ix01) * Cc;
            const float* D1 = g_xt + (size_t)((bb*Hh + iy11)*Ww + ix11) * Cc;
            float a0 = A0[lane],    b0 = B0[lane],    c0 = C0[lane],    d0 = D0[lane];
            float e0 = A0[lane+32], f0 = B0[lane+32], g0 = C0[lane+32], q0 = D0[lane+32];
            float a1 = A1[lane],    b1 = B1[lane],    c1 = C1[lane],    d1 = D1[lane];
            float e1 = A1[lane+32], f1 = B1[lane+32], g1 = C1[lane+32], q1 = D1[lane+32];
            samp[lane*33 + pp0]      = wA0*a0 + wB0*b0 + wC0*c0 + wD0*d0;
            samp[(lane+32)*33 + pp0] = wA0*e0 + wB0*f0 + wC0*g0 + wD0*q0;
            samp[lane*33 + pp1]      = wA1*a1 + wB1*b1 + wC1*c1 + wD1*d1;
            samp[(lane+32)*33 + pp1] = wA1*e1 + wB1*f1 + wC1*g1 + wD1*q1;
        }
        __syncthreads();
#pragma unroll 4
        for (int c = 0; c < 64; c++) {
            const float* srow = samp + c*33;
            float s0 = srow[ps], s1 = srow[ps + 16];
            ull p0 = f2pack(s0, s0), p1 = f2pack(s1, s1);
            const ulonglong2* wr = (const ulonglong2*)(ws + c*64 + og*8);
            ulonglong2 wa = wr[0], wb = wr[1];
            ffma2(acc[0], p0, wa.x); ffma2(acc[1], p0, wa.y);
            ffma2(acc[2], p0, wb.x); ffma2(acc[3], p0, wb.y);
            ffma2(acc[4], p1, wa.x); ffma2(acc[5], p1, wa.y);
            ffma2(acc[6], p1, wb.x); ffma2(acc[7], p1, wb.y);
        }
    }
#pragma unroll
    for (int k = 0; k < 2; k++) {
        int p = pq*32 + ps + 16*k;
#pragma unroll
        for (int j = 0; j < 4; j++) {
            float lo, hi; f2unpack(acc[k*4 + j], lo, hi);
            int o = og*8 + 2*j;
            out[(size_t)(bb*Oo + o    )*HW + h*Ww + p] = lo + __ldg(&dcn_b[o]);
            out[(size_t)(bb*Oo + o + 1)*HW + h*Ww + p] = hi + __ldg(&dcn_b[o+1]);
        }
    }
}

// ---------------- K3a: per-channel partial stats (2-stage, deterministic) ----------------
// grid (64 o, 8 parts), 256 thr; each part covers 2048 float4 of the channel.
__global__ void k_stats1(const float* __restrict__ out) {
    __shared__ float ssum[256], ssq[256];
    int o = blockIdx.x, part = blockIdx.y, t = threadIdx.x;
    const float4* po = (const float4*)out;
    float s = 0.f, q = 0.f;
#pragma unroll
    for (int u = 0; u < 8; u++) {
        int f = part*2048 + t + 256*u;     // float4 index within channel [0,16384)
        int b = f >> 12, j4 = f & 4095;    // 4096 float4 per (b,o) plane
        float4 v = po[(size_t)(b*Oo + o)*4096 + j4];
        s += v.x + v.y + v.z + v.w;
        q += v.x*v.x + v.y*v.y + v.z*v.z + v.w*v.w;
    }
    ssum[t] = s; ssq[t] = q;
    __syncthreads();
    for (int st = 128; st > 0; st >>= 1) {
        if (t < st) { ssum[t] += ssum[t+st]; ssq[t] += ssq[t+st]; }
        __syncthreads();
    }
    if (t == 0) {
        g_part[o*8 + part]       = ssum[0];
        g_part[512 + o*8 + part] = ssq[0];
    }
}
__global__ void k_stats2() {
    int o = threadIdx.x;   // 64 threads
    float s = 0.f, q = 0.f;
#pragma unroll
    for (int p = 0; p < 8; p++) { s += g_part[o*8 + p]; q += g_part[512 + o*8 + p]; }
    g_stats[o] = s; g_stats[64 + o] = q;
}

// ---------------- K4: BN + ReLU ----------------
__global__ void k_norm(float* __restrict__ out,
                       const float* __restrict__ gamma,
                       const float* __restrict__ beta) {
    int i4 = blockIdx.x * 256 + threadIdx.x;
    int idx = i4 * 4;
    int o = (idx >> 14) & 63;
    const float invN = 1.f / (float)(Bn*HW);
    float s = g_stats[o], q = g_stats[64 + o];
    float mu  = s * invN;
    float var = fmaf(q, invN, -mu*mu);
    float rstd = rsqrtf(var + 1e-5f) * __ldg(&gamma[o]);
    float bt = __ldg(&beta[o]);
    float4 v = *(float4*)(out + idx);
    v.x = fmaxf((v.x - mu)*rstd + bt, 0.f);
    v.y = fmaxf((v.y - mu)*rstd + bt, 0.f);
    v.z = fmaxf((v.z - mu)*rstd + bt, 0.f);
    v.w = fmaxf((v.w - mu)*rstd + bt, 0.f);
    *(float4*)(out + idx) = v;
}

// ---------------- launcher ----------------
extern "C" void kernel_launch(void* const* d_in, const int* in_sizes, int n_in,
                              void* d_out, int out_size) {
    const float* x        = (const float*)d_in[0];
    const float* offset_w = (const float*)d_in[1];
    const float* offset_b = (const float*)d_in[2];
    const float* dcn_w    = (const float*)d_in[3];
    const float* dcn_b    = (const float*)d_in[4];
    const float* gamma    = (const float*)d_in[5];
    const float* beta     = (const float*)d_in[6];
    float* out = (float*)d_out;

    k_transpose<<<dim3(512, Bn), dim3(32, 8)>>>(x);
    k_wt<<<144, 256>>>(dcn_w);
    k_owt<<<72, 256>>>(offset_w);
    k_offset<<<dim3(Hh, Bn, 2), 128>>>(offset_b);
    k_dcn<<<dim3(Hh, Bn, 4), 128>>>(dcn_b, out);
    k_stats1<<<dim3(Oo, 8), 256>>>(out);
    k_stats2<<<1, 64>>>();
    k_norm<<<(Bn*Oo*HW)/1024, 256>>>(out, gamma, beta);
}

// round 12
// speedup vs baseline: 1.4767x; 1.0009x over previous
#include <cuda_runtime.h>
#include <math.h>

#define Bn 4
#define Cc 64
#define Oo 64
#define Hh 128
#define Ww 128
#define HW (Hh*Ww)

typedef unsigned long long ull;

// ---------------- device scratch ----------------
__device__ float g_xt[Bn*HW*Cc];      // x as [b][h][w][c]
__device__ float g_wt[9*Cc*Oo];       // dcn_w as [tap][c][o]
__device__ float g_ow[9*Cc*32];       // offset_w as [tap][c][jq][8]
__device__ float g_offx[Bn*9*HW];
__device__ float g_offy[Bn*9*HW];
__device__ float g_mask[Bn*9*HW];
__device__ float g_part[2*Oo*8];      // partial sums [sum|sq][o][part]
__device__ float g_stats[2*Oo];

// ---------------- f32x2 helpers ----------------
__device__ __forceinline__ ull f2pack(float lo, float hi) {
    ull r;
    asm("mov.b64 %0, {%1, %2};" : "=l"(r)
        : "r"(__float_as_uint(lo)), "r"(__float_as_uint(hi)));
    return r;
}
__device__ __forceinline__ void f2unpack(ull v, float &lo, float &hi) {
    unsigned int a, b;
    asm("mov.b64 {%0, %1}, %2;" : "=r"(a), "=r"(b) : "l"(v));
    lo = __uint_as_float(a); hi = __uint_as_float(b);
}
__device__ __forceinline__ void ffma2(ull &d, ull a, ull b) {
    asm("fma.rn.f32x2 %0, %1, %2, %0;" : "+l"(d) : "l"(a), "l"(b));
}

// ---------------- K0: NCHW -> NHWC ----------------
__global__ void k_transpose(const float* __restrict__ x) {
    __shared__ float tile[32][65];
    int b = blockIdx.y, hw0 = blockIdx.x * 32;
    int tx = threadIdx.x, ty = threadIdx.y;
#pragma unroll
    for (int cc = 0; cc < 8; cc++) {
        int c = cc * 8 + ty;
        tile[tx][c] = x[(b*Cc + c)*HW + hw0 + tx];
    }
    __syncthreads();
#pragma unroll
    for (int rr = 0; rr < 4; rr++) {
        int hw = rr * 8 + ty;
        float* dst = g_xt + (size_t)(b*HW + hw0 + hw) * Cc;
        dst[tx]      = tile[hw][tx];
        dst[tx + 32] = tile[hw][tx + 32];
    }
}

// ---------------- K0b: weight re-layouts ----------------
__global__ void k_wt(const float* __restrict__ dcn_w) {
    int i = blockIdx.x * 256 + threadIdx.x;
    if (i < 9*Cc*Oo) {
        int o = i & 63, c = (i >> 6) & 63, k = i >> 12;
        g_wt[i] = dcn_w[(o*Cc + c)*9 + k];
    }
}
__global__ void k_owt(const float* __restrict__ ow) {
    int i = blockIdx.x * 256 + threadIdx.x;
    if (i < 9*Cc*32) {
        int slot = i & 31, c = (i >> 5) & 63, tap = i >> 11;
        int ky = tap / 3, kx = tap % 3;
        int jq = slot >> 3, idx = slot & 7;
        int j = jq*7 + idx;
        g_ow[i] = (idx < 7 && j < 27) ? ow[((j*Cc + c)*3 + ky)*3 + kx] : 0.f;
    }
}

// ---------------- K1: offset conv — verified best (unchanged) ----------------
__global__ void __launch_bounds__(128) k_offset(const float* __restrict__ ob) {
    __shared__ float wsm[64*32];     // [c][jq][8]   8 KB; per-c stride = 32 floats = 8 ull2
    __shared__ float xs[64*65];      // [c][px] stride 65  16.6 KB
    int t = threadIdx.x;
    int b = blockIdx.y, h = blockIdx.x, ph = blockIdx.z;
    int w0 = ph * 64;
    int lane = t & 31, wrp = t >> 5;
    int jq = wrp, ps = lane;
    int j0 = jq * 7;

    ull acc[8];
#pragma unroll
    for (int p = 0; p < 4; p++) {
        int j = j0 + 2*p;
        float lo = (j < 27)     ? __ldg(&ob[j])     : 0.f;
        float hi = (j + 1 < 27) ? __ldg(&ob[j + 1]) : 0.f;
        ull v = f2pack(lo, hi);
        acc[p] = v; acc[4 + p] = v;
    }

    for (int tap = 0; tap < 9; tap++) {
        int ky = tap / 3, kx = tap % 3;
        __syncthreads();
        {
            const float4* src = (const float4*)(g_ow + tap*64*32);
            float4* dst = (float4*)wsm;
            dst[t]       = src[t];
            dst[t + 128] = src[t + 128];
            dst[t + 256] = src[t + 256];
            dst[t + 384] = src[t + 384];
        }
        int y = h + ky - 1;
        if ((unsigned)y < Hh) {
            const float* xrow = g_xt + (size_t)(b*Hh + y) * Ww * Cc;
#pragma unroll
            for (int pp = wrp; pp < 64; pp += 4) {
                int xq = w0 + pp + kx - 1;
                bool v = ((unsigned)xq < Ww);
                const float* src = xrow + (size_t)(v ? xq : 0) * Cc;
                float v0 = v ? src[lane]      : 0.f;
                float v1 = v ? src[lane + 32] : 0.f;
                xs[lane*65 + pp]        = v0;
                xs[(lane + 32)*65 + pp] = v1;
            }
        } else {
#pragma unroll
            for (int pp = wrp; pp < 64; pp += 4) {
                xs[lane*65 + pp]        = 0.f;
                xs[(lane + 32)*65 + pp] = 0.f;
            }
        }
        __syncthreads();
        // per-c stride = 32 floats = 8 ulonglong2  -> wtap[c*8]
        const ulonglong2* wtap = (const ulonglong2*)(wsm + jq*8);
#pragma unroll 4
        for (int c = 0; c < 64; c++) {
            const float* srow = xs + c*65;
            float s0 = srow[ps], s1 = srow[ps + 32];
            ull p0 = f2pack(s0, s0), p1 = f2pack(s1, s1);
            ulonglong2 wA = wtap[c*8], wB = wtap[c*8 + 1];
            ffma2(acc[0], p0, wA.x); ffma2(acc[1], p0, wA.y);
            ffma2(acc[2], p0, wB.x); ffma2(acc[3], p0, wB.y);
            ffma2(acc[4], p1, wA.x); ffma2(acc[5], p1, wA.y);
            ffma2(acc[6], p1, wB.x); ffma2(acc[7], p1, wB.y);
        }
    }
#pragma unroll
    for (int k = 0; k < 2; k++) {
        int w = w0 + ps + 32*k;
        int base = (b*9)*HW + h*Ww + w;
        float a[8];
#pragma unroll
        for (int p = 0; p < 4; p++) f2unpack(acc[k*4 + p], a[2*p], a[2*p+1]);
#pragma unroll
        for (int u = 0; u < 7; u++) {
            int j = j0 + u;
            if (j < 9)        g_offx[base + j*HW]        = a[u];
            else if (j < 18)  g_offy[base + (j - 9)*HW]  = a[u];
            else if (j < 27)  g_mask[base + (j - 18)*HW] = 1.f / (1.f + expf(-a[u]));
        }
    }
}

// ---------------- K2: DCN — 128thr/32px + pre-staged offsets in smem ----------------
__global__ void __launch_bounds__(128, 8) k_dcn(const float* __restrict__ dcn_b,
                                                float* __restrict__ out) {
    __shared__ float ws[64*64];      // [c][o]  16 KB
    __shared__ float samp[64*33];    // [c][p] stride 33  8.45 KB
    __shared__ float soffx[9*32];    // offsets staged once per block (3.46 KB total)
    __shared__ float soffy[9*32];
    __shared__ float smask[9*32];

    int t    = threadIdx.x;
    int bb   = blockIdx.y, h = blockIdx.x, pq = blockIdx.z;
    int lane = t & 31,  wrp = t >> 5;
    int og   = t >> 4,  ps  = t & 15;

    // stage all 9 taps' offsets for this block's 32 pixels (coalesced 128B rows)
    for (int i = t; i < 288; i += 128) {
        int tap = i >> 5, px = i & 31;
        int gi = ((bb*9 + tap)*Hh + h)*Ww + pq*32 + px;
        soffx[i] = g_offx[gi];
        soffy[i] = g_offy[gi];
        smask[i] = g_mask[gi];
    }
    __syncthreads();

    ull acc[8];
#pragma unroll
    for (int i = 0; i < 8; i++) acc[i] = 0ULL;

    for (int tap = 0; tap < 9; tap++) {
        int ky = tap / 3, kx = tap % 3;
        __syncthreads();
        {
            const float4* src = (const float4*)(g_wt + tap*4096);
            float4* dst = (float4*)ws;
#pragma unroll
            for (int i = 0; i < 8; i++) dst[t + 128*i] = src[t + 128*i];
        }
#pragma unroll
        for (int i = 0; i < 8; i += 2) {
            int pp0 = wrp*8 + i, pp1 = pp0 + 1;
            int wq0 = pq*32 + pp0, wq1 = wq0 + 1;
            float oy0 = soffy[tap*32 + pp0], ox0 = soffx[tap*32 + pp0], m0 = smask[tap*32 + pp0];
            float oy1 = soffy[tap*32 + pp1], ox1 = soffx[tap*32 + pp1], m1 = smask[tap*32 + pp1];

            float py0 = (float)(h - 1 + ky) + oy0, px0 = (float)(wq0 - 1 + kx) + ox0;
            float py1 = (float)(h - 1 + ky) + oy1, px1 = (float)(wq1 - 1 + kx) + ox1;
            float y0f0 = floorf(py0), x0f0 = floorf(px0);
            float y0f1 = floorf(py1), x0f1 = floorf(px1);
            float wy0 = py0 - y0f0, wx0 = px0 - x0f0;
            float wy1 = py1 - y0f1, wx1 = px1 - x0f1;
            float hy00 = (y0f0 >=  0.f && y0f0 <= 127.f) ? (1.f - wy0)*m0 : 0.f;
            float hy10 = (y0f0 >= -1.f && y0f0 <= 126.f) ? wy0*m0        : 0.f;
            float gx00 = (x0f0 >=  0.f && x0f0 <= 127.f) ? (1.f - wx0)   : 0.f;
            float gx10 = (x0f0 >= -1.f && x0f0 <= 126.f) ? wx0           : 0.f;
            float hy01 = (y0f1 >=  0.f && y0f1 <= 127.f) ? (1.f - wy1)*m1 : 0.f;
            float hy11 = (y0f1 >= -1.f && y0f1 <= 126.f) ? wy1*m1        : 0.f;
            float gx01 = (x0f1 >=  0.f && x0f1 <= 127.f) ? (1.f - wx1)   : 0.f;
            float gx11 = (x0f1 >= -1.f && x0f1 <= 126.f) ? wx1           : 0.f;
            int iy00 = (int)fminf(fmaxf(y0f0,      0.f), 127.f);
            int iy10 = (int)fminf(fmaxf(y0f0 + 1.f,0.f), 127.f);
            int ix00 = (int)fminf(fmaxf(x0f0,      0.f), 127.f);
            int ix10 = (int)fminf(fmaxf(x0f0 + 1.f,0.f), 127.f);
            int iy01 = (int)fminf(fmaxf(y0f1,      0.f), 127.f);
            int iy11 = (int)fminf(fmaxf(y0f1 + 1.f,0.f), 127.f);
            int ix01 = (int)fminf(fmaxf(x0f1,      0.f), 127.f);
            int ix11 = (int)fminf(fmaxf(x0f1 + 1.f,0.f), 127.f);
            float wA0 = hy00*gx00, wB0 = hy00*gx10, wC0 = hy10*gx00, wD0 = hy10*gx10;
            float wA1 = hy01*gx01, wB1 = hy01*gx11, wC1 = hy11*gx01, wD1 = hy11*gx11;
            const float* A0 = g_xt + (size_t)((bb*Hh + iy00)*Ww + ix00) * Cc;
            const float* B0 = g_xt + (size_t)((bb*Hh + iy00)*Ww + ix10) * Cc;
            const float* C0 = g_xt + (size_t)((bb*Hh + iy10)*Ww + ix00) * Cc;
            const float* D0 = g_xt + (size_t)((bb*Hh + iy10)*Ww + ix10) * Cc;
            const float* A1 = g_xt + (size_t)((bb*Hh + iy01)*Ww + ix01) * Cc;
            const float* B1 = g_xt + (size_t)((bb*Hh + iy01)*Ww + ix11) * Cc;
            const float* C1 = g_xt + (size_t)((bb*Hh + iy11)*Ww + ix01) * Cc;
            const float* D1 = g_xt + (size_t)((bb*Hh + iy11)*Ww + ix11) * Cc;
            float a0 = A0[lane],    b0 = B0[lane],    c0 = C0[lane],    d0 = D0[lane];
            float e0 = A0[lane+32], f0 = B0[lane+32], g0 = C0[lane+32], q0 = D0[lane+32];
            float a1 = A1[lane],    b1 = B1[lane],    c1 = C1[lane],    d1 = D1[lane];
            float e1 = A1[lane+32], f1 = B1[lane+32], g1 = C1[lane+32], q1 = D1[lane+32];
            samp[lane*33 + pp0]      = wA0*a0 + wB0*b0 + wC0*c0 + wD0*d0;
            samp[(lane+32)*33 + pp0] = wA0*e0 + wB0*f0 + wC0*g0 + wD0*q0;
            samp[lane*33 + pp1]      = wA1*a1 + wB1*b1 + wC1*c1 + wD1*d1;
            samp[(lane+32)*33 + pp1] = wA1*e1 + wB1*f1 + wC1*g1 + wD1*q1;
        }
        __syncthreads();
#pragma unroll 4
        for (int c = 0; c < 64; c++) {
            const float* srow = samp + c*33;
            float s0 = srow[ps], s1 = srow[ps + 16];
            ull p0 = f2pack(s0, s0), p1 = f2pack(s1, s1);
            const ulonglong2* wr = (const ulonglong2*)(ws + c*64 + og*8);
            ulonglong2 wa = wr[0], wb = wr[1];
            ffma2(acc[0], p0, wa.x); ffma2(acc[1], p0, wa.y);
            ffma2(acc[2], p0, wb.x); ffma2(acc[3], p0, wb.y);
            ffma2(acc[4], p1, wa.x); ffma2(acc[5], p1, wa.y);
            ffma2(acc[6], p1, wb.x); ffma2(acc[7], p1, wb.y);
        }
    }
#pragma unroll
    for (int k = 0; k < 2; k++) {
        int p = pq*32 + ps + 16*k;
#pragma unroll
        for (int j = 0; j < 4; j++) {
            float lo, hi; f2unpack(acc[k*4 + j], lo, hi);
            int o = og*8 + 2*j;
            out[(size_t)(bb*Oo + o    )*HW + h*Ww + p] = lo + __ldg(&dcn_b[o]);
            out[(size_t)(bb*Oo + o + 1)*HW + h*Ww + p] = hi + __ldg(&dcn_b[o+1]);
        }
    }
}

// ---------------- K3a/b: per-channel stats (2-stage, deterministic) ----------------
__global__ void k_stats1(const float* __restrict__ out) {
    __shared__ float ssum[256], ssq[256];
    int o = blockIdx.x, part = blockIdx.y, t = threadIdx.x;
    const float4* po = (const float4*)out;
    float s = 0.f, q = 0.f;
#pragma unroll
    for (int u = 0; u < 8; u++) {
        int f = part*2048 + t + 256*u;
        int b = f >> 12, j4 = f & 4095;
        float4 v = po[(size_t)(b*Oo + o)*4096 + j4];
        s += v.x + v.y + v.z + v.w;
        q += v.x*v.x + v.y*v.y + v.z*v.z + v.w*v.w;
    }
    ssum[t] = s; ssq[t] = q;
    __syncthreads();
    for (int st = 128; st > 0; st >>= 1) {
        if (t < st) { ssum[t] += ssum[t+st]; ssq[t] += ssq[t+st]; }
        __syncthreads();
    }
    if (t == 0) {
        g_part[o*8 + part]       = ssum[0];
        g_part[512 + o*8 + part] = ssq[0];
    }
}
__global__ void k_stats2() {
    int o = threadIdx.x;
    float s = 0.f, q = 0.f;
#pragma unroll
    for (int p = 0; p < 8; p++) { s += g_part[o*8 + p]; q += g_part[512 + o*8 + p]; }
    g_stats[o] = s; g_stats[64 + o] = q;
}

// ---------------- K4: BN + ReLU ----------------
__global__ void k_norm(float* __restrict__ out,
                       const float* __restrict__ gamma,
                       const float* __restrict__ beta) {
    int i4 = blockIdx.x * 256 + threadIdx.x;
    int idx = i4 * 4;
    int o = (idx >> 14) & 63;
    const float invN = 1.f / (float)(Bn*HW);
    float s = g_stats[o], q = g_stats[64 + o];
    float mu  = s * invN;
    float var = fmaf(q, invN, -mu*mu);
    float rstd = rsqrtf(var + 1e-5f) * __ldg(&gamma[o]);
    float bt = __ldg(&beta[o]);
    float4 v = *(float4*)(out + idx);
    v.x = fmaxf((v.x - mu)*rstd + bt, 0.f);
    v.y = fmaxf((v.y - mu)*rstd + bt, 0.f);
    v.z = fmaxf((v.z - mu)*rstd + bt, 0.f);
    v.w = fmaxf((v.w - mu)*rstd + bt, 0.f);
    *(float4*)(out + idx) = v;
}

// ---------------- launcher ----------------
extern "C" void kernel_launch(void* const* d_in, const int* in_sizes, int n_in,
                              void* d_out, int out_size) {
    const float* x        = (const float*)d_in[0];
    const float* offset_w = (const float*)d_in[1];
    const float* offset_b = (const float*)d_in[2];
    const float* dcn_w    = (const float*)d_in[3];
    const float* dcn_b    = (const float*)d_in[4];
    const float* gamma    = (const float*)d_in[5];
    const float* beta     = (const float*)d_in[6];
    float* out = (float*)d_out;

    k_transpose<<<dim3(512, Bn), dim3(32, 8)>>>(x);
    k_wt<<<144, 256>>>(dcn_w);
    k_owt<<<72, 256>>>(offset_w);
    k_offset<<<dim3(Hh, Bn, 2), 128>>>(offset_b);
    k_dcn<<<dim3(Hh, Bn, 4), 128>>>(dcn_b, out);
    k_stats1<<<dim3(Oo, 8), 256>>>(out);
    k_stats2<<<1, 64>>>();
    k_norm<<<(Bn*Oo*HW)/1024, 256>>>(out, gamma, beta);
}

// round 13
// speedup vs baseline: 1.5065x; 1.0202x over previous
#include <cuda_runtime.h>
#include <math.h>

#define Bn 4
#define Cc 64
#define Oo 64
#define Hh 128
#define Ww 128
#define HW (Hh*Ww)

typedef unsigned long long ull;

// ---------------- device scratch ----------------
__device__ float g_xt[Bn*HW*Cc];      // x as [b][h][w][c]
__device__ float g_wt[9*Cc*Oo];       // dcn_w as [tap][c][o]
__device__ float g_ow[9*Cc*32];       // offset_w as [tap][c][jq][8]
__device__ float g_offx[Bn*9*HW];
__device__ float g_offy[Bn*9*HW];
__device__ float g_mask[Bn*9*HW];
__device__ float g_part[2*Oo*8];      // partial sums [sum|sq][o][part]
__device__ float g_stats[2*Oo];

// ---------------- f32x2 helpers ----------------
__device__ __forceinline__ ull f2pack(float lo, float hi) {
    ull r;
    asm("mov.b64 %0, {%1, %2};" : "=l"(r)
        : "r"(__float_as_uint(lo)), "r"(__float_as_uint(hi)));
    return r;
}
__device__ __forceinline__ void f2unpack(ull v, float &lo, float &hi) {
    unsigned int a, b;
    asm("mov.b64 {%0, %1}, %2;" : "=r"(a), "=r"(b) : "l"(v));
    lo = __uint_as_float(a); hi = __uint_as_float(b);
}
__device__ __forceinline__ void ffma2(ull &d, ull a, ull b) {
    asm("fma.rn.f32x2 %0, %1, %2, %0;" : "+l"(d) : "l"(a), "l"(b));
}

// ---------------- K0: NCHW -> NHWC ----------------
__global__ void k_transpose(const float* __restrict__ x) {
    __shared__ float tile[32][65];
    int b = blockIdx.y, hw0 = blockIdx.x * 32;
    int tx = threadIdx.x, ty = threadIdx.y;
#pragma unroll
    for (int cc = 0; cc < 8; cc++) {
        int c = cc * 8 + ty;
        tile[tx][c] = x[(b*Cc + c)*HW + hw0 + tx];
    }
    __syncthreads();
#pragma unroll
    for (int rr = 0; rr < 4; rr++) {
        int hw = rr * 8 + ty;
        float* dst = g_xt + (size_t)(b*HW + hw0 + hw) * Cc;
        dst[tx]      = tile[hw][tx];
        dst[tx + 32] = tile[hw][tx + 32];
    }
}

// ---------------- K0b: weight re-layouts ----------------
__global__ void k_wt(const float* __restrict__ dcn_w) {
    int i = blockIdx.x * 256 + threadIdx.x;
    if (i < 9*Cc*Oo) {
        int o = i & 63, c = (i >> 6) & 63, k = i >> 12;
        g_wt[i] = dcn_w[(o*Cc + c)*9 + k];
    }
}
__global__ void k_owt(const float* __restrict__ ow) {
    int i = blockIdx.x * 256 + threadIdx.x;
    if (i < 9*Cc*32) {
        int slot = i & 31, c = (i >> 5) & 63, tap = i >> 11;
        int ky = tap / 3, kx = tap % 3;
        int jq = slot >> 3, idx = slot & 7;
        int j = jq*7 + idx;
        g_ow[i] = (idx < 7 && j < 27) ? ow[((j*Cc + c)*3 + ky)*3 + kx] : 0.f;
    }
}

// ---------------- K1: offset conv — verified best (unchanged) ----------------
__global__ void __launch_bounds__(128) k_offset(const float* __restrict__ ob) {
    __shared__ float wsm[64*32];     // [c][jq][8]   8 KB; per-c stride = 32 floats = 8 ull2
    __shared__ float xs[64*65];      // [c][px] stride 65  16.6 KB
    int t = threadIdx.x;
    int b = blockIdx.y, h = blockIdx.x, ph = blockIdx.z;
    int w0 = ph * 64;
    int lane = t & 31, wrp = t >> 5;
    int jq = wrp, ps = lane;
    int j0 = jq * 7;

    ull acc[8];
#pragma unroll
    for (int p = 0; p < 4; p++) {
        int j = j0 + 2*p;
        float lo = (j < 27)     ? __ldg(&ob[j])     : 0.f;
        float hi = (j + 1 < 27) ? __ldg(&ob[j + 1]) : 0.f;
        ull v = f2pack(lo, hi);
        acc[p] = v; acc[4 + p] = v;
    }

    for (int tap = 0; tap < 9; tap++) {
        int ky = tap / 3, kx = tap % 3;
        __syncthreads();
        {
            const float4* src = (const float4*)(g_ow + tap*64*32);
            float4* dst = (float4*)wsm;
            dst[t]       = src[t];
            dst[t + 128] = src[t + 128];
            dst[t + 256] = src[t + 256];
            dst[t + 384] = src[t + 384];
        }
        int y = h + ky - 1;
        if ((unsigned)y < Hh) {
            const float* xrow = g_xt + (size_t)(b*Hh + y) * Ww * Cc;
#pragma unroll
            for (int pp = wrp; pp < 64; pp += 4) {
                int xq = w0 + pp + kx - 1;
                bool v = ((unsigned)xq < Ww);
                const float* src = xrow + (size_t)(v ? xq : 0) * Cc;
                float v0 = v ? src[lane]      : 0.f;
                float v1 = v ? src[lane + 32] : 0.f;
                xs[lane*65 + pp]        = v0;
                xs[(lane + 32)*65 + pp] = v1;
            }
        } else {
#pragma unroll
            for (int pp = wrp; pp < 64; pp += 4) {
                xs[lane*65 + pp]        = 0.f;
                xs[(lane + 32)*65 + pp] = 0.f;
            }
        }
        __syncthreads();
        // per-c stride = 32 floats = 8 ulonglong2  -> wtap[c*8]
        const ulonglong2* wtap = (const ulonglong2*)(wsm + jq*8);
#pragma unroll 4
        for (int c = 0; c < 64; c++) {
            const float* srow = xs + c*65;
            float s0 = srow[ps], s1 = srow[ps + 32];
            ull p0 = f2pack(s0, s0), p1 = f2pack(s1, s1);
            ulonglong2 wA = wtap[c*8], wB = wtap[c*8 + 1];
            ffma2(acc[0], p0, wA.x); ffma2(acc[1], p0, wA.y);
            ffma2(acc[2], p0, wB.x); ffma2(acc[3], p0, wB.y);
            ffma2(acc[4], p1, wA.x); ffma2(acc[5], p1, wA.y);
            ffma2(acc[6], p1, wB.x); ffma2(acc[7], p1, wB.y);
        }
    }
#pragma unroll
    for (int k = 0; k < 2; k++) {
        int w = w0 + ps + 32*k;
        int base = (b*9)*HW + h*Ww + w;
        float a[8];
#pragma unroll
        for (int p = 0; p < 4; p++) f2unpack(acc[k*4 + p], a[2*p], a[2*p+1]);
#pragma unroll
        for (int u = 0; u < 7; u++) {
            int j = j0 + u;
            if (j < 9)        g_offx[base + j*HW]        = a[u];
            else if (j < 18)  g_offy[base + (j - 9)*HW]  = a[u];
            else if (j < 27)  g_mask[base + (j - 18)*HW] = 1.f / (1.f + expf(-a[u]));
        }
    }
}

// ---------------- K2: DCN — adjacent-px mapping, LDS.64 samples ----------------
// block = (b, h, px-quarter): 32 px x 64 o; 128 threads.
// thread = 8 o (og*8..) x 2 adjacent px (2ps, 2ps+1).
__global__ void __launch_bounds__(128, 8) k_dcn(const float* __restrict__ dcn_b,
                                                float* __restrict__ out) {
    __shared__ float ws[64*64];      // [c][o]  16 KB
    __shared__ float samp[64*34];    // [c][p] stride 34 (even -> aligned float2 loads)
    __shared__ float soffx[9*32];    // offsets staged once per block
    __shared__ float soffy[9*32];
    __shared__ float smask[9*32];

    int t    = threadIdx.x;
    int bb   = blockIdx.y, h = blockIdx.x, pq = blockIdx.z;
    int lane = t & 31,  wrp = t >> 5;
    int og   = t >> 4,  ps  = t & 15;

    // stage all 9 taps' offsets for this block's 32 pixels (coalesced 128B rows)
    for (int i = t; i < 288; i += 128) {
        int tap = i >> 5, px = i & 31;
        int gi = ((bb*9 + tap)*Hh + h)*Ww + pq*32 + px;
        soffx[i] = g_offx[gi];
        soffy[i] = g_offy[gi];
        smask[i] = g_mask[gi];
    }
    __syncthreads();

    ull acc[8];                      // [px k 2][o-pair j 4]
#pragma unroll
    for (int i = 0; i < 8; i++) acc[i] = 0ULL;

    for (int tap = 0; tap < 9; tap++) {
        int ky = tap / 3, kx = tap % 3;
        __syncthreads();
        {
            const float4* src = (const float4*)(g_wt + tap*4096);
            float4* dst = (float4*)ws;
#pragma unroll
            for (int i = 0; i < 8; i++) dst[t + 128*i] = src[t + 128*i];
        }
#pragma unroll
        for (int i = 0; i < 8; i += 2) {
            int pp0 = wrp*8 + i, pp1 = pp0 + 1;
            int wq0 = pq*32 + pp0, wq1 = wq0 + 1;
            float oy0 = soffy[tap*32 + pp0], ox0 = soffx[tap*32 + pp0], m0 = smask[tap*32 + pp0];
            float oy1 = soffy[tap*32 + pp1], ox1 = soffx[tap*32 + pp1], m1 = smask[tap*32 + pp1];

            float py0 = (float)(h - 1 + ky) + oy0, px0 = (float)(wq0 - 1 + kx) + ox0;
            float py1 = (float)(h - 1 + ky) + oy1, px1 = (float)(wq1 - 1 + kx) + ox1;
            float y0f0 = floorf(py0), x0f0 = floorf(px0);
            float y0f1 = floorf(py1), x0f1 = floorf(px1);
            float wy0 = py0 - y0f0, wx0 = px0 - x0f0;
            float wy1 = py1 - y0f1, wx1 = px1 - x0f1;
            float hy00 = (y0f0 >=  0.f && y0f0 <= 127.f) ? (1.f - wy0)*m0 : 0.f;
            float hy10 = (y0f0 >= -1.f && y0f0 <= 126.f) ? wy0*m0        : 0.f;
            float gx00 = (x0f0 >=  0.f && x0f0 <= 127.f) ? (1.f - wx0)   : 0.f;
            float gx10 = (x0f0 >= -1.f && x0f0 <= 126.f) ? wx0           : 0.f;
            float hy01 = (y0f1 >=  0.f && y0f1 <= 127.f) ? (1.f - wy1)*m1 : 0.f;
            float hy11 = (y0f1 >= -1.f && y0f1 <= 126.f) ? wy1*m1        : 0.f;
            float gx01 = (x0f1 >=  0.f && x0f1 <= 127.f) ? (1.f - wx1)   : 0.f;
            float gx11 = (x0f1 >= -1.f && x0f1 <= 126.f) ? wx1           : 0.f;
            int iy00 = (int)fminf(fmaxf(y0f0,      0.f), 127.f);
            int iy10 = (int)fminf(fmaxf(y0f0 + 1.f,0.f), 127.f);
            int ix00 = (int)fminf(fmaxf(x0f0,      0.f), 127.f);
            int ix10 = (int)fminf(fmaxf(x0f0 + 1.f,0.f), 127.f);
            int iy01 = (int)fminf(fmaxf(y0f1,      0.f), 127.f);
            int iy11 = (int)fminf(fmaxf(y0f1 + 1.f,0.f), 127.f);
            int ix01 = (int)fminf(fmaxf(x0f1,      0.f), 127.f);
            int ix11 = (int)fminf(fmaxf(x0f1 + 1.f,0.f), 127.f);
            float wA0 = hy00*gx00, wB0 = hy00*gx10, wC0 = hy10*gx00, wD0 = hy10*gx10;
            float wA1 = hy01*gx01, wB1 = hy01*gx11, wC1 = hy11*gx01, wD1 = hy11*gx11;
            const float* A0 = g_xt + (size_t)((bb*Hh + iy00)*Ww + ix00) * Cc;
            const float* B0 = g_xt + (size_t)((bb*Hh + iy00)*Ww + ix10) * Cc;
            const float* C0 = g_xt + (size_t)((bb*Hh + iy10)*Ww + ix00) * Cc;
            const float* D0 = g_xt + (size_t)((bb*Hh + iy10)*Ww + ix10) * Cc;
            const float* A1 = g_xt + (size_t)((bb*Hh + iy01)*Ww + ix01) * Cc;
            const float* B1 = g_xt + (size_t)((bb*Hh + iy01)*Ww + ix11) * Cc;
            const float* C1 = g_xt + (size_t)((bb*Hh + iy11)*Ww + ix01) * Cc;
            const float* D1 = g_xt + (size_t)((bb*Hh + iy11)*Ww + ix11) * Cc;
            float a0 = A0[lane],    b0 = B0[lane],    c0 = C0[lane],    d0 = D0[lane];
            float e0 = A0[lane+32], f0 = B0[lane+32], g0 = C0[lane+32], q0 = D0[lane+32];
            float a1 = A1[lane],    b1 = B1[lane],    c1 = C1[lane],    d1 = D1[lane];
            float e1 = A1[lane+32], f1 = B1[lane+32], g1 = C1[lane+32], q1 = D1[lane+32];
            samp[lane*34 + pp0]      = wA0*a0 + wB0*b0 + wC0*c0 + wD0*d0;
            samp[(lane+32)*34 + pp0] = wA0*e0 + wB0*f0 + wC0*g0 + wD0*q0;
            samp[lane*34 + pp1]      = wA1*a1 + wB1*b1 + wC1*c1 + wD1*d1;
            samp[(lane+32)*34 + pp1] = wA1*e1 + wB1*f1 + wC1*g1 + wD1*q1;
        }
        __syncthreads();
        // GEMM per c: 1 LDS.64 (both px) + 2 pack + 2 broadcast LDS.128 + 8 FFMA2
#pragma unroll 4
        for (int c = 0; c < 64; c++) {
            float2 sv = *(const float2*)(samp + c*34 + 2*ps);   // px 2ps, 2ps+1
            ull p0 = f2pack(sv.x, sv.x), p1 = f2pack(sv.y, sv.y);
            const ulonglong2* wr = (const ulonglong2*)(ws + c*64 + og*8);
            ulonglong2 wa = wr[0], wb = wr[1];
            ffma2(acc[0], p0, wa.x); ffma2(acc[1], p0, wa.y);
            ffma2(acc[2], p0, wb.x); ffma2(acc[3], p0, wb.y);
            ffma2(acc[4], p1, wa.x); ffma2(acc[5], p1, wa.y);
            ffma2(acc[6], p1, wb.x); ffma2(acc[7], p1, wb.y);
        }
    }
    // stores: per o, float2 over the adjacent px pair
    {
        int prow = h*Ww + pq*32 + 2*ps;
#pragma unroll
        for (int j = 0; j < 4; j++) {
            float lo0, hi0, lo1, hi1;
            f2unpack(acc[j],     lo0, hi0);   // px 2ps   : (o, o+1)
            f2unpack(acc[4 + j], lo1, hi1);   // px 2ps+1 : (o, o+1)
            int o = og*8 + 2*j;
            float b0 = __ldg(&dcn_b[o]), b1 = __ldg(&dcn_b[o+1]);
            float2 v0 = make_float2(lo0 + b0, lo1 + b0);
            float2 v1 = make_float2(hi0 + b1, hi1 + b1);
            *(float2*)(out + (size_t)(bb*Oo + o    )*HW + prow) = v0;
            *(float2*)(out + (size_t)(bb*Oo + o + 1)*HW + prow) = v1;
        }
    }
}

// ---------------- K3a/b: per-channel stats (2-stage, deterministic) ----------------
__global__ void k_stats1(const float* __restrict__ out) {
    __shared__ float ssum[256], ssq[256];
    int o = blockIdx.x, part = blockIdx.y, t = threadIdx.x;
    const float4* po = (const float4*)out;
    float s = 0.f, q = 0.f;
#pragma unroll
    for (int u = 0; u < 8; u++) {
        int f = part*2048 + t + 256*u;
        int b = f >> 12, j4 = f & 4095;
        float4 v = po[(size_t)(b*Oo + o)*4096 + j4];
        s += v.x + v.y + v.z + v.w;
        q += v.x*v.x + v.y*v.y + v.z*v.z + v.w*v.w;
    }
    ssum[t] = s; ssq[t] = q;
    __syncthreads();
    for (int st = 128; st > 0; st >>= 1) {
        if (t < st) { ssum[t] += ssum[t+st]; ssq[t] += ssq[t+st]; }
        __syncthreads();
    }
    if (t == 0) {
        g_part[o*8 + part]       = ssum[0];
        g_part[512 + o*8 + part] = ssq[0];
    }
}
__global__ void k_stats2() {
    int o = threadIdx.x;
    float s = 0.f, q = 0.f;
#pragma unroll
    for (int p = 0; p < 8; p++) { s += g_part[o*8 + p]; q += g_part[512 + o*8 + p]; }
    g_stats[o] = s; g_stats[64 + o] = q;
}

// ---------------- K4: BN + ReLU ----------------
__global__ void k_norm(float* __restrict__ out,
                       const float* __restrict__ gamma,
                       const float* __restrict__ beta) {
    int i4 = blockIdx.x * 256 + threadIdx.x;
    int idx = i4 * 4;
    int o = (idx >> 14) & 63;
    const float invN = 1.f / (float)(Bn*HW);
    float s = g_stats[o], q = g_stats[64 + o];
    float mu  = s * invN;
    float var = fmaf(q, invN, -mu*mu);
    float rstd = rsqrtf(var + 1e-5f) * __ldg(&gamma[o]);
    float bt = __ldg(&beta[o]);
    float4 v = *(float4*)(out + idx);
    v.x = fmaxf((v.x - mu)*rstd + bt, 0.f);
    v.y = fmaxf((v.y - mu)*rstd + bt, 0.f);
    v.z = fmaxf((v.z - mu)*rstd + bt, 0.f);
    v.w = fmaxf((v.w - mu)*rstd + bt, 0.f);
    *(float4*)(out + idx) = v;
}

// ---------------- launcher ----------------
extern "C" void kernel_launch(void* const* d_in, const int* in_sizes, int n_in,
                              void* d_out, int out_size) {
    const float* x        = (const float*)d_in[0];
    const float* offset_w = (const float*)d_in[1];
    const float* offset_b = (const float*)d_in[2];
    const float* dcn_w    = (const float*)d_in[3];
    const float* dcn_b    = (const float*)d_in[4];
    const float* gamma    = (const float*)d_in[5];
    const float* beta     = (const float*)d_in[6];
    float* out = (float*)d_out;

    k_transpose<<<dim3(512, Bn), dim3(32, 8)>>>(x);
    k_wt<<<144, 256>>>(dcn_w);
    k_owt<<<72, 256>>>(offset_w);
    k_offset<<<dim3(Hh, Bn, 2), 128>>>(offset_b);
    k_dcn<<<dim3(Hh, Bn, 4), 128>>>(dcn_b, out);
    k_stats1<<<dim3(Oo, 8), 256>>>(out);
    k_stats2<<<1, 64>>>();
    k_norm<<<(Bn*Oo*HW)/1024, 256>>>(out, gamma, beta);
}

// round 14
// speedup vs baseline: 1.5442x; 1.0250x over previous
#include <cuda_runtime.h>
#include <math.h>

#define Bn 4
#define Cc 64
#define Oo 64
#define Hh 128
#define Ww 128
#define HW (Hh*Ww)

typedef unsigned long long ull;

// ---------------- device scratch ----------------
__device__ float g_xt[Bn*HW*Cc];      // x as [b][h][w][c]
__device__ float g_wt[9*Cc*Oo];       // dcn_w as [tap][c][o]
__device__ float g_ow[9*Cc*32];       // offset_w as [tap][c][jq][8]
__device__ float g_offx[Bn*9*HW];
__device__ float g_offy[Bn*9*HW];
__device__ float g_mask[Bn*9*HW];
__device__ float g_part[2*Oo*8];      // partial sums [sum|sq][o][part]
__device__ float g_stats[2*Oo];

// ---------------- f32x2 helpers ----------------
__device__ __forceinline__ ull f2pack(float lo, float hi) {
    ull r;
    asm("mov.b64 %0, {%1, %2};" : "=l"(r)
        : "r"(__float_as_uint(lo)), "r"(__float_as_uint(hi)));
    return r;
}
__device__ __forceinline__ void f2unpack(ull v, float &lo, float &hi) {
    unsigned int a, b;
    asm("mov.b64 {%0, %1}, %2;" : "=r"(a), "=r"(b) : "l"(v));
    lo = __uint_as_float(a); hi = __uint_as_float(b);
}
__device__ __forceinline__ void ffma2(ull &d, ull a, ull b) {
    asm("fma.rn.f32x2 %0, %1, %2, %0;" : "+l"(d) : "l"(a), "l"(b));
}

// ---------------- K0: NCHW -> NHWC ----------------
__global__ void k_transpose(const float* __restrict__ x) {
    __shared__ float tile[32][65];
    int b = blockIdx.y, hw0 = blockIdx.x * 32;
    int tx = threadIdx.x, ty = threadIdx.y;
#pragma unroll
    for (int cc = 0; cc < 8; cc++) {
        int c = cc * 8 + ty;
        tile[tx][c] = x[(b*Cc + c)*HW + hw0 + tx];
    }
    __syncthreads();
#pragma unroll
    for (int rr = 0; rr < 4; rr++) {
        int hw = rr * 8 + ty;
        float* dst = g_xt + (size_t)(b*HW + hw0 + hw) * Cc;
        dst[tx]      = tile[hw][tx];
        dst[tx + 32] = tile[hw][tx + 32];
    }
}

// ---------------- K0b: weight re-layouts ----------------
__global__ void k_wt(const float* __restrict__ dcn_w) {
    int i = blockIdx.x * 256 + threadIdx.x;
    if (i < 9*Cc*Oo) {
        int o = i & 63, c = (i >> 6) & 63, k = i >> 12;
        g_wt[i] = dcn_w[(o*Cc + c)*9 + k];
    }
}
__global__ void k_owt(const float* __restrict__ ow) {
    int i = blockIdx.x * 256 + threadIdx.x;
    if (i < 9*Cc*32) {
        int slot = i & 31, c = (i >> 5) & 63, tap = i >> 11;
        int ky = tap / 3, kx = tap % 3;
        int jq = slot >> 3, idx = slot & 7;
        int j = jq*7 + idx;
        g_ow[i] = (idx < 7 && j < 27) ? ow[((j*Cc + c)*3 + ky)*3 + kx] : 0.f;
    }
}

// ---------------- K1: offset conv — adjacent-px pairs (LDS.64 samples) ----------------
// block = (b, h, px-half): 64 px; 128 threads = 4 jq warps x 32 px-pair lanes.
// thread = 7 j (jq quarter) x 2 adjacent px (2ps, 2ps+1).
__global__ void __launch_bounds__(128) k_offset(const float* __restrict__ ob) {
    __shared__ __align__(16) float wsm[64*32];   // [c][jq][8]   8 KB
    __shared__ __align__(16) float xs[64*66];    // [c][px] stride 66 (even -> float2)
    int t = threadIdx.x;
    int b = blockIdx.y, h = blockIdx.x, ph = blockIdx.z;
    int w0 = ph * 64;
    int lane = t & 31, wrp = t >> 5;
    int jq = wrp, ps = lane;
    int j0 = jq * 7;

    ull acc[8];                      // [px 2][j-pair 4]
#pragma unroll
    for (int p = 0; p < 4; p++) {
        int j = j0 + 2*p;
        float lo = (j < 27)     ? __ldg(&ob[j])     : 0.f;
        float hi = (j + 1 < 27) ? __ldg(&ob[j + 1]) : 0.f;
        ull v = f2pack(lo, hi);
        acc[p] = v; acc[4 + p] = v;
    }

    for (int tap = 0; tap < 9; tap++) {
        int ky = tap / 3, kx = tap % 3;
        __syncthreads();
        {
            const float4* src = (const float4*)(g_ow + tap*64*32);
            float4* dst = (float4*)wsm;
            dst[t]       = src[t];
            dst[t + 128] = src[t + 128];
            dst[t + 256] = src[t + 256];
            dst[t + 384] = src[t + 384];
        }
        int y = h + ky - 1;
        if ((unsigned)y < Hh) {
            const float* xrow = g_xt + (size_t)(b*Hh + y) * Ww * Cc;
#pragma unroll
            for (int pp = wrp; pp < 64; pp += 4) {
                int xq = w0 + pp + kx - 1;
                bool v = ((unsigned)xq < Ww);
                const float* src = xrow + (size_t)(v ? xq : 0) * Cc;
                float v0 = v ? src[lane]      : 0.f;
                float v1 = v ? src[lane + 32] : 0.f;
                xs[lane*66 + pp]        = v0;
                xs[(lane + 32)*66 + pp] = v1;
            }
        } else {
#pragma unroll
            for (int pp = wrp; pp < 64; pp += 4) {
                xs[lane*66 + pp]        = 0.f;
                xs[(lane + 32)*66 + pp] = 0.f;
            }
        }
        __syncthreads();
        // per c: 1 LDS.64 (both px) + 2 broadcast LDS.128 + 2 pack + 8 FFMA2
        const ulonglong2* wtap = (const ulonglong2*)(wsm + jq*8);
#pragma unroll 4
        for (int c = 0; c < 64; c++) {
            float2 sv = *(const float2*)(xs + c*66 + 2*ps);   // px 2ps, 2ps+1
            ull p0 = f2pack(sv.x, sv.x), p1 = f2pack(sv.y, sv.y);
            ulonglong2 wA = wtap[c*8], wB = wtap[c*8 + 1];
            ffma2(acc[0], p0, wA.x); ffma2(acc[1], p0, wA.y);
            ffma2(acc[2], p0, wB.x); ffma2(acc[3], p0, wB.y);
            ffma2(acc[4], p1, wA.x); ffma2(acc[5], p1, wA.y);
            ffma2(acc[6], p1, wB.x); ffma2(acc[7], p1, wB.y);
        }
    }
#pragma unroll
    for (int k = 0; k < 2; k++) {
        int w = w0 + 2*ps + k;
        int base = (b*9)*HW + h*Ww + w;
        float a[8];
#pragma unroll
        for (int p = 0; p < 4; p++) f2unpack(acc[k*4 + p], a[2*p], a[2*p+1]);
#pragma unroll
        for (int u = 0; u < 7; u++) {
            int j = j0 + u;
            if (j < 9)        g_offx[base + j*HW]        = a[u];
            else if (j < 18)  g_offy[base + (j - 9)*HW]  = a[u];
            else if (j < 27)  g_mask[base + (j - 18)*HW] = 1.f / (1.f + expf(-a[u]));
        }
    }
}

// ---------------- K2: DCN — 256 thr, 64 px x 64 o (staging amortized 2x) ----------------
// warp = 8 px (4 adjacent pairs) x 64 o; lane: og = lane>>2 (8 o-chunks), pr = lane&3.
__global__ void __launch_bounds__(256, 4) k_dcn(const float* __restrict__ dcn_b,
                                                float* __restrict__ out) {
    __shared__ __align__(16) float ws[64*64];    // [c][o]  16 KB
    __shared__ __align__(16) float samp[64*66];  // [c][px] stride 66  16.9 KB
    __shared__ float soffx[9*64];                // offsets staged once per block
    __shared__ float soffy[9*64];
    __shared__ float smask[9*64];

    int t    = threadIdx.x;
    int bb   = blockIdx.y, h = blockIdx.x, pq = blockIdx.z;   // pq in {0,1}
    int lane = t & 31,  wrp = t >> 5;                          // wrp 0-7
    int og   = lane >> 2, pr = lane & 3;
    int pxp  = wrp*4 + pr;                                     // px-pair index 0-31

    // stage all 9 taps' offsets for this block's 64 pixels (coalesced)
    for (int i = t; i < 576; i += 256) {
        int tap = i >> 6, px = i & 63;
        int gi = ((bb*9 + tap)*Hh + h)*Ww + pq*64 + px;
        soffx[i] = g_offx[gi];
        soffy[i] = g_offy[gi];
        smask[i] = g_mask[gi];
    }
    __syncthreads();

    ull acc[8];                      // [px k 2][o-pair j 4]
#pragma unroll
    for (int i = 0; i < 8; i++) acc[i] = 0ULL;

    for (int tap = 0; tap < 9; tap++) {
        int ky = tap / 3, kx = tap % 3;
        __syncthreads();
        {   // stage tap weights: 1024 float4, 4 per thread
            const float4* src = (const float4*)(g_wt + tap*4096);
            float4* dst = (float4*)ws;
#pragma unroll
            for (int i = 0; i < 4; i++) dst[t + 256*i] = src[t + 256*i];
        }
        // gather: warp owns 8 px, 2-px batches, lane = channel
#pragma unroll
        for (int i = 0; i < 8; i += 2) {
            int pp0 = wrp*8 + i, pp1 = pp0 + 1;
            int wq0 = pq*64 + pp0, wq1 = wq0 + 1;
            float oy0 = soffy[tap*64 + pp0], ox0 = soffx[tap*64 + pp0], m0 = smask[tap*64 + pp0];
            float oy1 = soffy[tap*64 + pp1], ox1 = soffx[tap*64 + pp1], m1 = smask[tap*64 + pp1];

            float py0 = (float)(h - 1 + ky) + oy0, px0 = (float)(wq0 - 1 + kx) + ox0;
            float py1 = (float)(h - 1 + ky) + oy1, px1 = (float)(wq1 - 1 + kx) + ox1;
            float y0f0 = floorf(py0), x0f0 = floorf(px0);
            float y0f1 = floorf(py1), x0f1 = floorf(px1);
            float wy0 = py0 - y0f0, wx0 = px0 - x0f0;
            float wy1 = py1 - y0f1, wx1 = px1 - x0f1;
            float hy00 = (y0f0 >=  0.f && y0f0 <= 127.f) ? (1.f - wy0)*m0 : 0.f;
            float hy10 = (y0f0 >= -1.f && y0f0 <= 126.f) ? wy0*m0        : 0.f;
            float gx00 = (x0f0 >=  0.f && x0f0 <= 127.f) ? (1.f - wx0)   : 0.f;
            float gx10 = (x0f0 >= -1.f && x0f0 <= 126.f) ? wx0           : 0.f;
            float hy01 = (y0f1 >=  0.f && y0f1 <= 127.f) ? (1.f - wy1)*m1 : 0.f;
            float hy11 = (y0f1 >= -1.f && y0f1 <= 126.f) ? wy1*m1        : 0.f;
            float gx01 = (x0f1 >=  0.f && x0f1 <= 127.f) ? (1.f - wx1)   : 0.f;
            float gx11 = (x0f1 >= -1.f && x0f1 <= 126.f) ? wx1           : 0.f;
            int iy00 = (int)fminf(fmaxf(y0f0,      0.f), 127.f);
            int iy10 = (int)fminf(fmaxf(y0f0 + 1.f,0.f), 127.f);
            int ix00 = (int)fminf(fmaxf(x0f0,      0.f), 127.f);
            int ix10 = (int)fminf(fmaxf(x0f0 + 1.f,0.f), 127.f);
            int iy01 = (int)fminf(fmaxf(y0f1,      0.f), 127.f);
            int iy11 = (int)fminf(fmaxf(y0f1 + 1.f,0.f), 127.f);
            int ix01 = (int)fminf(fmaxf(x0f1,      0.f), 127.f);
            int ix11 = (int)fminf(fmaxf(x0f1 + 1.f,0.f), 127.f);
            float wA0 = hy00*gx00, wB0 = hy00*gx10, wC0 = hy10*gx00, wD0 = hy10*gx10;
            float wA1 = hy01*gx01, wB1 = hy01*gx11, wC1 = hy11*gx01, wD1 = hy11*gx11;
            const float* A0 = g_xt + (size_t)((bb*Hh + iy00)*Ww + ix00) * Cc;
            const float* B0 = g_xt + (size_t)((bb*Hh + iy00)*Ww + ix10) * Cc;
            const float* C0 = g_xt + (size_t)((bb*Hh + iy10)*Ww + ix00) * Cc;
            const float* D0 = g_xt + (size_t)((bb*Hh + iy10)*Ww + ix10) * Cc;
            const float* A1 = g_xt + (size_t)((bb*Hh + iy01)*Ww + ix01) * Cc;
            const float* B1 = g_xt + (size_t)((bb*Hh + iy01)*Ww + ix11) * Cc;
            const float* C1 = g_xt + (size_t)((bb*Hh + iy11)*Ww + ix01) * Cc;
            const float* D1 = g_xt + (size_t)((bb*Hh + iy11)*Ww + ix11) * Cc;
            float a0 = A0[lane],    b0 = B0[lane],    c0 = C0[lane],    d0 = D0[lane];
            float e0 = A0[lane+32], f0 = B0[lane+32], g0 = C0[lane+32], q0 = D0[lane+32];
            float a1 = A1[lane],    b1 = B1[lane],    c1 = C1[lane],    d1 = D1[lane];
            float e1 = A1[lane+32], f1 = B1[lane+32], g1 = C1[lane+32], q1 = D1[lane+32];
            samp[lane*66 + pp0]      = wA0*a0 + wB0*b0 + wC0*c0 + wD0*d0;
            samp[(lane+32)*66 + pp0] = wA0*e0 + wB0*f0 + wC0*g0 + wD0*q0;
            samp[lane*66 + pp1]      = wA1*a1 + wB1*b1 + wC1*c1 + wD1*d1;
            samp[(lane+32)*66 + pp1] = wA1*e1 + wB1*f1 + wC1*g1 + wD1*q1;
        }
        __syncthreads();
        // GEMM per c: 1 LDS.64 (px pair) + 2 LDS.128 weights + 2 pack + 8 FFMA2
#pragma unroll 4
        for (int c = 0; c < 64; c++) {
            float2 sv = *(const float2*)(samp + c*66 + 2*pxp);   // px 2pxp, 2pxp+1
            ull p0 = f2pack(sv.x, sv.x), p1 = f2pack(sv.y, sv.y);
            const ulonglong2* wr = (const ulonglong2*)(ws + c*64 + og*8);
            ulonglong2 wa = wr[0], wb = wr[1];
            ffma2(acc[0], p0, wa.x); ffma2(acc[1], p0, wa.y);
            ffma2(acc[2], p0, wb.x); ffma2(acc[3], p0, wb.y);
            ffma2(acc[4], p1, wa.x); ffma2(acc[5], p1, wa.y);
            ffma2(acc[6], p1, wb.x); ffma2(acc[7], p1, wb.y);
        }
    }
    // stores: per o, float2 over the adjacent px pair
    {
        int prow = h*Ww + pq*64 + 2*pxp;
#pragma unroll
        for (int j = 0; j < 4; j++) {
            float lo0, hi0, lo1, hi1;
            f2unpack(acc[j],     lo0, hi0);   // px 2pxp   : (o, o+1)
            f2unpack(acc[4 + j], lo1, hi1);   // px 2pxp+1 : (o, o+1)
            int o = og*8 + 2*j;
            float b0 = __ldg(&dcn_b[o]), b1 = __ldg(&dcn_b[o+1]);
            float2 v0 = make_float2(lo0 + b0, lo1 + b0);
            float2 v1 = make_float2(hi0 + b1, hi1 + b1);
            *(float2*)(out + (size_t)(bb*Oo + o    )*HW + prow) = v0;
            *(float2*)(out + (size_t)(bb*Oo + o + 1)*HW + prow) = v1;
        }
    }
}

// ---------------- K3a/b: per-channel stats (2-stage, deterministic) ----------------
__global__ void k_stats1(const float* __restrict__ out) {
    __shared__ float ssum[256], ssq[256];
    int o = blockIdx.x, part = blockIdx.y, t = threadIdx.x;
    const float4* po = (const float4*)out;
    float s = 0.f, q = 0.f;
#pragma unroll
    for (int u = 0; u < 8; u++) {
        int f = part*2048 + t + 256*u;
        int b = f >> 12, j4 = f & 4095;
        float4 v = po[(size_t)(b*Oo + o)*4096 + j4];
        s += v.x + v.y + v.z + v.w;
        q += v.x*v.x + v.y*v.y + v.z*v.z + v.w*v.w;
    }
    ssum[t] = s; ssq[t] = q;
    __syncthreads();
    for (int st = 128; st > 0; st >>= 1) {
        if (t < st) { ssum[t] += ssum[t+st]; ssq[t] += ssq[t+st]; }
        __syncthreads();
    }
    if (t == 0) {
        g_part[o*8 + part]       = ssum[0];
        g_part[512 + o*8 + part] = ssq[0];
    }
}
__global__ void k_stats2() {
    int o = threadIdx.x;
    float s = 0.f, q = 0.f;
#pragma unroll
    for (int p = 0; p < 8; p++) { s += g_part[o*8 + p]; q += g_part[512 + o*8 + p]; }
    g_stats[o] = s; g_stats[64 + o] = q;
}

// ---------------- K4: BN + ReLU ----------------
__global__ void k_norm(float* __restrict__ out,
                       const float* __restrict__ gamma,
                       const float* __restrict__ beta) {
    int i4 = blockIdx.x * 256 + threadIdx.x;
    int idx = i4 * 4;
    int o = (idx >> 14) & 63;
    const float invN = 1.f / (float)(Bn*HW);
    float s = g_stats[o], q = g_stats[64 + o];
    float mu  = s * invN;
    float var = fmaf(q, invN, -mu*mu);
    float rstd = rsqrtf(var + 1e-5f) * __ldg(&gamma[o]);
    float bt = __ldg(&beta[o]);
    float4 v = *(float4*)(out + idx);
    v.x = fmaxf((v.x - mu)*rstd + bt, 0.f);
    v.y = fmaxf((v.y - mu)*rstd + bt, 0.f);
    v.z = fmaxf((v.z - mu)*rstd + bt, 0.f);
    v.w = fmaxf((v.w - mu)*rstd + bt, 0.f);
    *(float4*)(out + idx) = v;
}

// ---------------- launcher ----------------
extern "C" void kernel_launch(void* const* d_in, const int* in_sizes, int n_in,
                              void* d_out, int out_size) {
    const float* x        = (const float*)d_in[0];
    const float* offset_w = (const float*)d_in[1];
    const float* offset_b = (const float*)d_in[2];
    const float* dcn_w    = (const float*)d_in[3];
    const float* dcn_b    = (const float*)d_in[4];
    const float* gamma    = (const float*)d_in[5];
    const float* beta     = (const float*)d_in[6];
    float* out = (float*)d_out;

    k_transpose<<<dim3(512, Bn), dim3(32, 8)>>>(x);
    k_wt<<<144, 256>>>(dcn_w);
    k_owt<<<72, 256>>>(offset_w);
    k_offset<<<dim3(Hh, Bn, 2), 128>>>(offset_b);
    k_dcn<<<dim3(Hh, Bn, 2), 256>>>(dcn_b, out);
    k_stats1<<<dim3(Oo, 8), 256>>>(out);
    k_stats2<<<1, 64>>>();
    k_norm<<<(Bn*Oo*HW)/1024, 256>>>(out, gamma, beta);
}

// round 15
// speedup vs baseline: 1.6144x; 1.0455x over previous
#include <cuda_runtime.h>
#include <math.h>

#define Bn 4
#define Cc 64
#define Oo 64
#define Hh 128
#define Ww 128
#define HW (Hh*Ww)

typedef unsigned long long ull;

// ---------------- device scratch ----------------
__device__ float g_xt[Bn*HW*Cc];      // x as [b][h][w][c]
__device__ float g_wt[9*Cc*Oo];       // dcn_w as [tap][c][o]
__device__ float g_ow[9*Cc*32];       // offset_w as [tap][c][jq][8]
__device__ float g_offx[Bn*9*HW];
__device__ float g_offy[Bn*9*HW];
__device__ float g_mask[Bn*9*HW];
__device__ float g_part[2*Oo*8];      // partial sums [sum|sq][o][part]
__device__ float g_stats[2*Oo];

// ---------------- f32x2 helpers ----------------
__device__ __forceinline__ ull f2pack(float lo, float hi) {
    ull r;
    asm("mov.b64 %0, {%1, %2};" : "=l"(r)
        : "r"(__float_as_uint(lo)), "r"(__float_as_uint(hi)));
    return r;
}
__device__ __forceinline__ void f2unpack(ull v, float &lo, float &hi) {
    unsigned int a, b;
    asm("mov.b64 {%0, %1}, %2;" : "=r"(a), "=r"(b) : "l"(v));
    lo = __uint_as_float(a); hi = __uint_as_float(b);
}
__device__ __forceinline__ void ffma2(ull &d, ull a, ull b) {
    asm("fma.rn.f32x2 %0, %1, %2, %0;" : "+l"(d) : "l"(a), "l"(b));
}

// ---------------- K0: NCHW -> NHWC ----------------
__global__ void k_transpose(const float* __restrict__ x) {
    __shared__ float tile[32][65];
    int b = blockIdx.y, hw0 = blockIdx.x * 32;
    int tx = threadIdx.x, ty = threadIdx.y;
#pragma unroll
    for (int cc = 0; cc < 8; cc++) {
        int c = cc * 8 + ty;
        tile[tx][c] = x[(b*Cc + c)*HW + hw0 + tx];
    }
    __syncthreads();
#pragma unroll
    for (int rr = 0; rr < 4; rr++) {
        int hw = rr * 8 + ty;
        float* dst = g_xt + (size_t)(b*HW + hw0 + hw) * Cc;
        dst[tx]      = tile[hw][tx];
        dst[tx + 32] = tile[hw][tx + 32];
    }
}

// ---------------- K0b: weight re-layouts ----------------
__global__ void k_wt(const float* __restrict__ dcn_w) {
    int i = blockIdx.x * 256 + threadIdx.x;
    if (i < 9*Cc*Oo) {
        int o = i & 63, c = (i >> 6) & 63, k = i >> 12;
        g_wt[i] = dcn_w[(o*Cc + c)*9 + k];
    }
}
__global__ void k_owt(const float* __restrict__ ow) {
    int i = blockIdx.x * 256 + threadIdx.x;
    if (i < 9*Cc*32) {
        int slot = i & 31, c = (i >> 5) & 63, tap = i >> 11;
        int ky = tap / 3, kx = tap % 3;
        int jq = slot >> 3, idx = slot & 7;
        int j = jq*7 + idx;
        g_ow[i] = (idx < 7 && j < 27) ? ow[((j*Cc + c)*3 + ky)*3 + kx] : 0.f;
    }
}

// ---------------- K1: offset conv — ky-factored staging (3 stages, halo window) ----------------
// block = (b, h, px-half): 64 px; 128 threads = 4 jq warps x 32 px-pair lanes.
// Per ky: stage row y=h+ky-1 once (66-px halo), weights for 3 kx taps together.
// GEMM per c: 2 LDS.64 samples (window 2ps..2ps+3) + 6 LDS.128 weights + 24 FFMA2.
__global__ void __launch_bounds__(128) k_offset(const float* __restrict__ ob) {
    __shared__ __align__(16) float wsm[3*64*32];  // [kx][c][jq*8]  24 KB
    __shared__ __align__(16) float xs[64*68];     // [c][halo px 0..65] stride 68  17.4 KB
    int t = threadIdx.x;
    int b = blockIdx.y, h = blockIdx.x, ph = blockIdx.z;
    int w0 = ph * 64;
    int lane = t & 31, wrp = t >> 5;
    int jq = wrp, ps = lane;
    int j0 = jq * 7;

    ull acc[8];                      // [px k 2][j-pair 4]
#pragma unroll
    for (int p = 0; p < 4; p++) {
        int j = j0 + 2*p;
        float lo = (j < 27)     ? __ldg(&ob[j])     : 0.f;
        float hi = (j + 1 < 27) ? __ldg(&ob[j + 1]) : 0.f;
        ull v = f2pack(lo, hi);
        acc[p] = v; acc[4 + p] = v;
    }

    for (int ky = 0; ky < 3; ky++) {
        __syncthreads();
        {   // stage weights for taps ky*3 + {0,1,2}: 6144 floats = 1536 float4
            const float4* src = (const float4*)(g_ow + (ky*3)*2048);
            float4* dst = (float4*)wsm;
#pragma unroll
            for (int i = 0; i < 12; i++) dst[t + 128*i] = src[t + 128*i];
        }
        // stage x row with halo: xs[c][pp] = x[y][w0-1+pp][c], pp in [0,66)
        int y = h + ky - 1;
        if ((unsigned)y < Hh) {
            const float* xrow = g_xt + (size_t)(b*Hh + y) * Ww * Cc;
            for (int pp = wrp; pp < 66; pp += 4) {
                int xq = w0 + pp - 1;
                bool v = ((unsigned)xq < Ww);
                const float* src = xrow + (size_t)(v ? xq : 0) * Cc;
                float v0 = v ? src[lane]      : 0.f;
                float v1 = v ? src[lane + 32] : 0.f;
                xs[lane*68 + pp]        = v0;
                xs[(lane + 32)*68 + pp] = v1;
            }
        } else {
            for (int pp = wrp; pp < 66; pp += 4) {
                xs[lane*68 + pp]        = 0.f;
                xs[(lane + 32)*68 + pp] = 0.f;
            }
        }
        __syncthreads();
#pragma unroll 2
        for (int c = 0; c < 64; c++) {
            float2 sA = *(const float2*)(xs + c*68 + 2*ps);       // xs[2ps], xs[2ps+1]
            float2 sB = *(const float2*)(xs + c*68 + 2*ps + 2);   // xs[2ps+2], xs[2ps+3]
            // output px0 = w0+2ps   needs xs[2ps+kx]   = {sA.x, sA.y, sB.x}
            // output px1 = w0+2ps+1 needs xs[2ps+1+kx] = {sA.y, sB.x, sB.y}
            float smp0[3] = {sA.x, sA.y, sB.x};
            float smp1[3] = {sA.y, sB.x, sB.y};
#pragma unroll
            for (int kx = 0; kx < 3; kx++) {
                const ulonglong2* wt =
                    (const ulonglong2*)(wsm + kx*2048 + c*32 + jq*8);
                ulonglong2 wA = wt[0], wB = wt[1];
                ull p0 = f2pack(smp0[kx], smp0[kx]);
                ull p1 = f2pack(smp1[kx], smp1[kx]);
                ffma2(acc[0], p0, wA.x); ffma2(acc[1], p0, wA.y);
                ffma2(acc[2], p0, wB.x); ffma2(acc[3], p0, wB.y);
                ffma2(acc[4], p1, wA.x); ffma2(acc[5], p1, wA.y);
                ffma2(acc[6], p1, wB.x); ffma2(acc[7], p1, wB.y);
            }
        }
    }
#pragma unroll
    for (int k = 0; k < 2; k++) {
        int w = w0 + 2*ps + k;
        int base = (b*9)*HW + h*Ww + w;
        float a[8];
#pragma unroll
        for (int p = 0; p < 4; p++) f2unpack(acc[k*4 + p], a[2*p], a[2*p+1]);
#pragma unroll
        for (int u = 0; u < 7; u++) {
            int j = j0 + u;
            if (j < 9)        g_offx[base + j*HW]        = a[u];
            else if (j < 18)  g_offy[base + (j - 9)*HW]  = a[u];
            else if (j < 27)  g_mask[base + (j - 18)*HW] = 1.f / (1.f + expf(-a[u]));
        }
    }
}

// ---------------- K2: DCN — verified best (248.5us config, unchanged) ----------------
__global__ void __launch_bounds__(256, 4) k_dcn(const float* __restrict__ dcn_b,
                                                float* __restrict__ out) {
    __shared__ __align__(16) float ws[64*64];    // [c][o]  16 KB
    __shared__ __align__(16) float samp[64*66];  // [c][px] stride 66  16.9 KB
    __shared__ float soffx[9*64];                // offsets staged once per block
    __shared__ float soffy[9*64];
    __shared__ float smask[9*64];

    int t    = threadIdx.x;
    int bb   = blockIdx.y, h = blockIdx.x, pq = blockIdx.z;   // pq in {0,1}
    int lane = t & 31,  wrp = t >> 5;                          // wrp 0-7
    int og   = lane >> 2, pr = lane & 3;
    int pxp  = wrp*4 + pr;                                     // px-pair index 0-31

    // stage all 9 taps' offsets for this block's 64 pixels (coalesced)
    for (int i = t; i < 576; i += 256) {
        int tap = i >> 6, px = i & 63;
        int gi = ((bb*9 + tap)*Hh + h)*Ww + pq*64 + px;
        soffx[i] = g_offx[gi];
        soffy[i] = g_offy[gi];
        smask[i] = g_mask[gi];
    }
    __syncthreads();

    ull acc[8];                      // [px k 2][o-pair j 4]
#pragma unroll
    for (int i = 0; i < 8; i++) acc[i] = 0ULL;

    for (int tap = 0; tap < 9; tap++) {
        int ky = tap / 3, kx = tap % 3;
        __syncthreads();
        {   // stage tap weights: 1024 float4, 4 per thread
            const float4* src = (const float4*)(g_wt + tap*4096);
            float4* dst = (float4*)ws;
#pragma unroll
            for (int i = 0; i < 4; i++) dst[t + 256*i] = src[t + 256*i];
        }
        // gather: warp owns 8 px, 2-px batches, lane = channel
#pragma unroll
        for (int i = 0; i < 8; i += 2) {
            int pp0 = wrp*8 + i, pp1 = pp0 + 1;
            int wq0 = pq*64 + pp0, wq1 = wq0 + 1;
            float oy0 = soffy[tap*64 + pp0], ox0 = soffx[tap*64 + pp0], m0 = smask[tap*64 + pp0];
            float oy1 = soffy[tap*64 + pp1], ox1 = soffx[tap*64 + pp1], m1 = smask[tap*64 + pp1];

            float py0 = (float)(h - 1 + ky) + oy0, px0 = (float)(wq0 - 1 + kx) + ox0;
            float py1 = (float)(h - 1 + ky) + oy1, px1 = (float)(wq1 - 1 + kx) + ox1;
            float y0f0 = floorf(py0), x0f0 = floorf(px0);
            float y0f1 = floorf(py1), x0f1 = floorf(px1);
            float wy0 = py0 - y0f0, wx0 = px0 - x0f0;
            float wy1 = py1 - y0f1, wx1 = px1 - x0f1;
            float hy00 = (y0f0 >=  0.f && y0f0 <= 127.f) ? (1.f - wy0)*m0 : 0.f;
            float hy10 = (y0f0 >= -1.f && y0f0 <= 126.f) ? wy0*m0        : 0.f;
            float gx00 = (x0f0 >=  0.f && x0f0 <= 127.f) ? (1.f - wx0)   : 0.f;
            float gx10 = (x0f0 >= -1.f && x0f0 <= 126.f) ? wx0           : 0.f;
            float hy01 = (y0f1 >=  0.f && y0f1 <= 127.f) ? (1.f - wy1)*m1 : 0.f;
            float hy11 = (y0f1 >= -1.f && y0f1 <= 126.f) ? wy1*m1        : 0.f;
            float gx01 = (x0f1 >=  0.f && x0f1 <= 127.f) ? (1.f - wx1)   : 0.f;
            float gx11 = (x0f1 >= -1.f && x0f1 <= 126.f) ? wx1           : 0.f;
            int iy00 = (int)fminf(fmaxf(y0f0,      0.f), 127.f);
            int iy10 = (int)fminf(fmaxf(y0f0 + 1.f,0.f), 127.f);
            int ix00 = (int)fminf(fmaxf(x0f0,      0.f), 127.f);
            int ix10 = (int)fminf(fmaxf(x0f0 + 1.f,0.f), 127.f);
            int iy01 = (int)fminf(fmaxf(y0f1,      0.f), 127.f);
            int iy11 = (int)fminf(fmaxf(y0f1 + 1.f,0.f), 127.f);
            int ix01 = (int)fminf(fmaxf(x0f1,      0.f), 127.f);
            int ix11 = (int)fminf(fmaxf(x0f1 + 1.f,0.f), 127.f);
            float wA0 = hy00*gx00, wB0 = hy00*gx10, wC0 = hy10*gx00, wD0 = hy10*gx10;
            float wA1 = hy01*gx01, wB1 = hy01*gx11, wC1 = hy11*gx01, wD1 = hy11*gx11;
            const float* A0 = g_xt + (size_t)((bb*Hh + iy00)*Ww + ix00) * Cc;
            const float* B0 = g_xt + (size_t)((bb*Hh + iy00)*Ww + ix10) * Cc;
            const float* C0 = g_xt + (size_t)((bb*Hh + iy10)*Ww + ix00) * Cc;
            const float* D0 = g_xt + (size_t)((bb*Hh + iy10)*Ww + ix10) * Cc;
            const float* A1 = g_xt + (size_t)((bb*Hh + iy01)*Ww + ix01) * Cc;
            const float* B1 = g_xt + (size_t)((bb*Hh + iy01)*Ww + ix11) * Cc;
            const float* C1 = g_xt + (size_t)((bb*Hh + iy11)*Ww + ix01) * Cc;
            const float* D1 = g_xt + (size_t)((bb*Hh + iy11)*Ww + ix11) * Cc;
            float a0 = A0[lane],    b0 = B0[lane],    c0 = C0[lane],    d0 = D0[lane];
            float e0 = A0[lane+32], f0 = B0[lane+32], g0 = C0[lane+32], q0 = D0[lane+32];
            float a1 = A1[lane],    b1 = B1[lane],    c1 = C1[lane],    d1 = D1[lane];
            float e1 = A1[lane+32], f1 = B1[lane+32], g1 = C1[lane+32], q1 = D1[lane+32];
            samp[lane*66 + pp0]      = wA0*a0 + wB0*b0 + wC0*c0 + wD0*d0;
            samp[(lane+32)*66 + pp0] = wA0*e0 + wB0*f0 + wC0*g0 + wD0*q0;
            samp[lane*66 + pp1]      = wA1*a1 + wB1*b1 + wC1*c1 + wD1*d1;
            samp[(lane+32)*66 + pp1] = wA1*e1 + wB1*f1 + wC1*g1 + wD1*q1;
        }
        __syncthreads();
        // GEMM per c: 1 LDS.64 (px pair) + 2 LDS.128 weights + 2 pack + 8 FFMA2
#pragma unroll 4
        for (int c = 0; c < 64; c++) {
            float2 sv = *(const float2*)(samp + c*66 + 2*pxp);   // px 2pxp, 2pxp+1
            ull p0 = f2pack(sv.x, sv.x), p1 = f2pack(sv.y, sv.y);
            const ulonglong2* wr = (const ulonglong2*)(ws + c*64 + og*8);
            ulonglong2 wa = wr[0], wb = wr[1];
            ffma2(acc[0], p0, wa.x); ffma2(acc[1], p0, wa.y);
            ffma2(acc[2], p0, wb.x); ffma2(acc[3], p0, wb.y);
            ffma2(acc[4], p1, wa.x); ffma2(acc[5], p1, wa.y);
            ffma2(acc[6], p1, wb.x); ffma2(acc[7], p1, wb.y);
        }
    }
    // stores: per o, float2 over the adjacent px pair
    {
        int prow = h*Ww + pq*64 + 2*pxp;
#pragma unroll
        for (int j = 0; j < 4; j++) {
            float lo0, hi0, lo1, hi1;
            f2unpack(acc[j],     lo0, hi0);   // px 2pxp   : (o, o+1)
            f2unpack(acc[4 + j], lo1, hi1);   // px 2pxp+1 : (o, o+1)
            int o = og*8 + 2*j;
            float b0 = __ldg(&dcn_b[o]), b1 = __ldg(&dcn_b[o+1]);
            float2 v0 = make_float2(lo0 + b0, lo1 + b0);
            float2 v1 = make_float2(hi0 + b1, hi1 + b1);
            *(float2*)(out + (size_t)(bb*Oo + o    )*HW + prow) = v0;
            *(float2*)(out + (size_t)(bb*Oo + o + 1)*HW + prow) = v1;
        }
    }
}

// ---------------- K3a/b: per-channel stats (2-stage, deterministic) ----------------
__global__ void k_stats1(const float* __restrict__ out) {
    __shared__ float ssum[256], ssq[256];
    int o = blockIdx.x, part = blockIdx.y, t = threadIdx.x;
    const float4* po = (const float4*)out;
    float s = 0.f, q = 0.f;
#pragma unroll
    for (int u = 0; u < 8; u++) {
        int f = part*2048 + t + 256*u;
        int b = f >> 12, j4 = f & 4095;
        float4 v = po[(size_t)(b*Oo + o)*4096 + j4];
        s += v.x + v.y + v.z + v.w;
        q += v.x*v.x + v.y*v.y + v.z*v.z + v.w*v.w;
    }
    ssum[t] = s; ssq[t] = q;
    __syncthreads();
    for (int st = 128; st > 0; st >>= 1) {
        if (t < st) { ssum[t] += ssum[t+st]; ssq[t] += ssq[t+st]; }
        __syncthreads();
    }
    if (t == 0) {
        g_part[o*8 + part]       = ssum[0];
        g_part[512 + o*8 + part] = ssq[0];
    }
}
__global__ void k_stats2() {
    int o = threadIdx.x;
    float s = 0.f, q = 0.f;
#pragma unroll
    for (int p = 0; p < 8; p++) { s += g_part[o*8 + p]; q += g_part[512 + o*8 + p]; }
    g_stats[o] = s; g_stats[64 + o] = q;
}

// ---------------- K4: BN + ReLU ----------------
__global__ void k_norm(float* __restrict__ out,
                       const float* __restrict__ gamma,
                       const float* __restrict__ beta) {
    int i4 = blockIdx.x * 256 + threadIdx.x;
    int idx = i4 * 4;
    int o = (idx >> 14) & 63;
    const float invN = 1.f / (float)(Bn*HW);
    float s = g_stats[o], q = g_stats[64 + o];
    float mu  = s * invN;
    float var = fmaf(q, invN, -mu*mu);
    float rstd = rsqrtf(var + 1e-5f) * __ldg(&gamma[o]);
    float bt = __ldg(&beta[o]);
    float4 v = *(float4*)(out + idx);
    v.x = fmaxf((v.x - mu)*rstd + bt, 0.f);
    v.y = fmaxf((v.y - mu)*rstd + bt, 0.f);
    v.z = fmaxf((v.z - mu)*rstd + bt, 0.f);
    v.w = fmaxf((v.w - mu)*rstd + bt, 0.f);
    *(float4*)(out + idx) = v;
}

// ---------------- launcher ----------------
extern "C" void kernel_launch(void* const* d_in, const int* in_sizes, int n_in,
                              void* d_out, int out_size) {
    const float* x        = (const float*)d_in[0];
    const float* offset_w = (const float*)d_in[1];
    const float* offset_b = (const float*)d_in[2];
    const float* dcn_w    = (const float*)d_in[3];
    const float* dcn_b    = (const float*)d_in[4];
    const float* gamma    = (const float*)d_in[5];
    const float* beta     = (const float*)d_in[6];
    float* out = (float*)d_out;

    k_transpose<<<dim3(512, Bn), dim3(32, 8)>>>(x);
    k_wt<<<144, 256>>>(dcn_w);
    k_owt<<<72, 256>>>(offset_w);
    k_offset<<<dim3(Hh, Bn, 2), 128>>>(offset_b);
    k_dcn<<<dim3(Hh, Bn, 2), 256>>>(dcn_b, out);
    k_stats1<<<dim3(Oo, 8), 256>>>(out);
    k_stats2<<<1, 64>>>();
    k_norm<<<(Bn*Oo*HW)/1024, 256>>>(out, gamma, beta);
}